// round 14
// baseline (speedup 1.0000x reference)
#include <cuda_runtime.h>
#include <cstdint>
#include <math.h>

// ---------------- problem constants ----------------
#define N_RAYS_C   4096
#define PPR_C      64
#define VD_C       12
#define GRID_C     128
#define ACT_SHIFT_C (-4.5951199f)   // log(1/(1-0.01) - 1)

#define AP 212
#define BP 132
#define KT 16
#define NTHREADS 512
#define NPTS 128                      // 2 rays per block
#define NBLOCKS (N_RAYS_C / 2)
#define NBUF 3                        // TMA ring depth

// ---- smem layout (floats) ----
#define OFF_A     0
#define OFF_B     (NPTS*AP)                    // 27136
#define OFF_WS    (OFF_B + NPTS*BP)            // 44032
#define OFF_W3    (OFF_WS + NBUF*KT*128)       // 50176 (dt_wo 384 + bias 3 -> 388)
#define OFF_W3B   (OFF_W3 + 388)               // dec_w1 192 + bias 3 -> 196
#define OFF_PD    (OFF_W3B + 196)
#define OFF_ALP   (OFF_PD + NPTS*3)
#define OFF_WGT   (OFF_ALP + NPTS)
#define OFF_RGB   (OFF_WGT + NPTS)
#define OFF_VE    (OFF_RGB + NPTS*3)
#define OFF_ALAST (OFF_VE + 48)
#define OFF_TI    (OFF_ALAST + 8)
#define OFF_TFR   (OFF_TI + NPTS*3)
#define OFF_MB    (OFF_TFR + NPTS*3)           // 3 x u64 mbarriers (6 floats), pad 8
#define SMEM_FLOATS (OFF_MB + 8)
#define SMEM_BYTES  (SMEM_FLOATS * 4)

// ---------------- device scratch (static: no allocation) ----------------
__device__ float g_feat_t[(size_t)GRID_C * GRID_C * GRID_C * VD_C];  // [X,Y,Z,C]
__device__ float g_pool2t[(size_t)64 * 64 * 64 * VD_C];
__device__ float g_pool4t[(size_t)32 * 32 * 32 * VD_C];
__device__ float g_tf[64];   // 60 used

// ---------------- f32x2 / ptx helpers ----------------
__device__ __forceinline__ void ffma2(unsigned long long& d, unsigned long long a,
                                      unsigned long long b) {
    asm("fma.rn.f32x2 %0, %1, %2, %0;" : "+l"(d) : "l"(a), "l"(b));
}
__device__ __forceinline__ unsigned long long dup2(float x) {
    unsigned long long r;
    asm("mov.b64 %0, {%1, %1};" : "=l"(r) : "f"(x));
    return r;
}
__device__ __forceinline__ uint32_t smem_u32(const void* p) {
    return (uint32_t)__cvta_generic_to_shared(p);
}
__device__ __forceinline__ void mbar_init(uint32_t a, uint32_t cnt) {
    asm volatile("mbarrier.init.shared.b64 [%0], %1;" :: "r"(a), "r"(cnt) : "memory");
}
__device__ __forceinline__ void mbar_expect(uint32_t a, uint32_t bytes) {
    asm volatile("mbarrier.arrive.expect_tx.shared.b64 _, [%0], %1;"
                 :: "r"(a), "r"(bytes) : "memory");
}
__device__ __forceinline__ void mbar_wait(uint32_t a, uint32_t parity) {
    asm volatile(
        "{\n\t"
        ".reg .pred P;\n"
        "LW%=:\n\t"
        "mbarrier.try_wait.parity.acquire.cta.shared::cta.b64 P, [%0], %1;\n\t"
        "@!P bra LW%=;\n\t"
        "}"
        :: "r"(a), "r"(parity) : "memory");
}
__device__ __forceinline__ void bulk_g2s(uint32_t dst, const float* src,
                                         uint32_t bytes, uint32_t mbar) {
    asm volatile(
        "cp.async.bulk.shared::cluster.global.mbarrier::complete_tx::bytes "
        "[%0], [%1], %2, [%3];"
        :: "r"(dst), "l"(src), "r"(bytes), "r"(mbar) : "memory");
}

// ---------------- grid transpose + pooling (transposed layouts) ----------------
__global__ void transpose_feat(const float* __restrict__ f) {
    int v = blockIdx.x * blockDim.x + threadIdx.x;
    const int V = GRID_C * GRID_C * GRID_C;
    if (v >= V) return;
    float vals[VD_C];
    #pragma unroll
    for (int c = 0; c < VD_C; ++c) vals[c] = __ldg(f + (size_t)c * V + v);
    float* dst = g_feat_t + (size_t)v * VD_C;
    #pragma unroll
    for (int q = 0; q < 3; ++q)
        *reinterpret_cast<float4*>(dst + q * 4) =
            make_float4(vals[q * 4], vals[q * 4 + 1], vals[q * 4 + 2], vals[q * 4 + 3]);
}

__global__ void pool2t_kernel() {
    int v = blockIdx.x * blockDim.x + threadIdx.x;
    if (v >= 64 * 64 * 64) return;
    int z = v & 63, y = (v >> 6) & 63, x = v >> 12;
    float acc[VD_C];
    #pragma unroll
    for (int c = 0; c < VD_C; ++c) acc[c] = 0.f;
    #pragma unroll
    for (int d = 0; d < 8; ++d) {
        int dx = d >> 2, dy = (d >> 1) & 1, dz = d & 1;
        const float* s = g_feat_t +
            ((((size_t)(2 * x + dx) * 128 + (2 * y + dy)) * 128 + (2 * z + dz)) * VD_C);
        #pragma unroll
        for (int q = 0; q < 3; ++q) {
            float4 b = *reinterpret_cast<const float4*>(s + q * 4);
            acc[q * 4 + 0] += b.x; acc[q * 4 + 1] += b.y;
            acc[q * 4 + 2] += b.z; acc[q * 4 + 3] += b.w;
        }
    }
    float* dst = g_pool2t + (size_t)v * VD_C;
    #pragma unroll
    for (int q = 0; q < 3; ++q)
        *reinterpret_cast<float4*>(dst + q * 4) =
            make_float4(acc[q * 4] * 0.125f, acc[q * 4 + 1] * 0.125f,
                        acc[q * 4 + 2] * 0.125f, acc[q * 4 + 3] * 0.125f);
}

__global__ void pool4t_kernel() {
    int v = blockIdx.x * blockDim.x + threadIdx.x;
    if (v >= 32 * 32 * 32) return;
    int z = v & 31, y = (v >> 5) & 31, x = v >> 10;
    float acc[VD_C];
    #pragma unroll
    for (int c = 0; c < VD_C; ++c) acc[c] = 0.f;
    #pragma unroll
    for (int d = 0; d < 8; ++d) {
        int dx = d >> 2, dy = (d >> 1) & 1, dz = d & 1;
        const float* s = g_pool2t +
            ((((size_t)(2 * x + dx) * 64 + (2 * y + dy)) * 64 + (2 * z + dz)) * VD_C);
        #pragma unroll
        for (int q = 0; q < 3; ++q) {
            float4 b = *reinterpret_cast<const float4*>(s + q * 4);
            acc[q * 4 + 0] += b.x; acc[q * 4 + 1] += b.y;
            acc[q * 4 + 2] += b.z; acc[q * 4 + 3] += b.w;
        }
    }
    float* dst = g_pool4t + (size_t)v * VD_C;
    #pragma unroll
    for (int q = 0; q < 3; ++q)
        *reinterpret_cast<float4*>(dst + q * 4) =
            make_float4(acc[q * 4] * 0.125f, acc[q * 4 + 1] * 0.125f,
                        acc[q * 4 + 2] * 0.125f, acc[q * 4 + 3] * 0.125f);
}

// ---------------- timenet (tiny, runs once) ----------------
__global__ void timenet_kernel(const float* __restrict__ ft,
                               const float* __restrict__ w0, const float* __restrict__ b0,
                               const float* __restrict__ w1, const float* __restrict__ b1) {
    __shared__ float temb[9];
    __shared__ float h[128];
    int tid = threadIdx.x;
    if (tid == 0) {
        float t = ft[0];
        temb[0] = t;
        #pragma unroll
        for (int k = 0; k < 4; ++k) {
            temb[1 + k] = sinf(t * (float)(1 << k));
            temb[5 + k] = cosf(t * (float)(1 << k));
        }
    }
    __syncthreads();
    {
        float v = b0[tid];
        #pragma unroll
        for (int k = 0; k < 9; ++k) v = fmaf(temb[k], w0[k * 128 + tid], v);
        h[tid] = fmaxf(v, 0.f);
    }
    __syncthreads();
    if (tid < 60) {
        float v = b1[tid];
        for (int k = 0; k < 128; ++k) v = fmaf(h[k], w1[k * 60 + tid], v);
        g_tf[tid] = v;
    }
}

// ---------------- trilerp setup ----------------
__device__ __forceinline__ void tri_setup(const float* pd, int D, int* ii, float* ff) {
    float dim = (float)(D - 1);
    float hi = dim - 1e-4f;
    #pragma unroll
    for (int c = 0; c < 3; ++c) {
        float t = (pd[c] + 1.f) * 0.5f * dim;
        t = fminf(fmaxf(t, 0.f), hi);
        float fl = floorf(t);
        ii[c] = (int)fl;
        ff[c] = t - fl;
    }
}

__device__ __forceinline__ float tri_gather1(const float* __restrict__ g, int D,
                                             int ix, int iy, int iz,
                                             float fx, float fy, float fz) {
    size_t sx = (size_t)D * D;
    int sy = D;
    const float* b = g + (size_t)ix * sx + (size_t)iy * sy + iz;
    float v000 = __ldg(b),            v001 = __ldg(b + 1);
    float v010 = __ldg(b + sy),       v011 = __ldg(b + sy + 1);
    float v100 = __ldg(b + sx),       v101 = __ldg(b + sx + 1);
    float v110 = __ldg(b + sx + sy),  v111 = __ldg(b + sx + sy + 1);
    float c00 = v000 + (v001 - v000) * fz;
    float c01 = v010 + (v011 - v010) * fz;
    float c10 = v100 + (v101 - v100) * fz;
    float c11 = v110 + (v111 - v110) * fz;
    float c0 = c00 + (c01 - c00) * fy;
    float c1 = c10 + (c11 - c10) * fy;
    return c0 + (c1 - c0) * fx;
}

__device__ __forceinline__ float4 lerp4(float4 a, float4 b, float t) {
    return make_float4(a.x + (b.x - a.x) * t, a.y + (b.y - a.y) * t,
                       a.z + (b.z - a.z) * t, a.w + (b.w - a.w) * t);
}

// ---------------- register-tiled f32x2 GEMM, 3-deep TMA ring ----------------
// NPTS points x OUT cols; 512 threads: ci = tid&15 (CP cols), pi = tid>>4 (4 pts)
template <int OUT, int ACT>
__device__ __forceinline__ void mlp_layer(
    const float* __restrict__ W, const float* __restrict__ bias,
    const float* __restrict__ xs, int xp, int INA, int INP,
    float* __restrict__ ys, int yp,
    float* __restrict__ ws, const uint32_t* mb, int* ph, int tid) {
    constexpr int CP = OUT / 16;
    constexpr int NP = CP / 2;
    const int ci = tid & 15;
    const int pi = tid >> 4;
    unsigned long long acc[4][NP];
    #pragma unroll
    for (int r = 0; r < 4; ++r)
        #pragma unroll
        for (int j = 0; j < NP; ++j) acc[r][j] = 0ull;

    const int ntiles = INP / KT;

    auto issue = [&](int t) {
        if (tid == 0) {
            int rows = INA - t * KT; if (rows > KT) rows = KT;
            uint32_t bytes = (uint32_t)rows * OUT * 4u;
            int buf = t % NBUF;
            mbar_expect(mb[buf], bytes);
            bulk_g2s(smem_u32(ws + buf * (KT * 128)), W + (size_t)t * KT * OUT,
                     bytes, mb[buf]);
        }
    };

    issue(0);
    if (ntiles > 1) issue(1);
    for (int t = 0; t < ntiles; ++t) {
        const int buf = t % NBUF;
        mbar_wait(mb[buf], (uint32_t)ph[buf]); ph[buf] ^= 1;
        __syncthreads();                      // all threads past tile t-1 compute
        if (t + 2 < ntiles) issue(t + 2);

        const float* xb = xs + (size_t)(pi * 4) * xp + t * KT;
        const float* wb = ws + buf * (KT * 128);
        #pragma unroll
        for (int k4 = 0; k4 < KT; k4 += 4) {
            float4 xv[4];
            #pragma unroll
            for (int r = 0; r < 4; ++r)
                xv[r] = *reinterpret_cast<const float4*>(xb + r * xp + k4);
            #pragma unroll
            for (int kk = 0; kk < 4; ++kk) {
                unsigned long long xx[4];
                #pragma unroll
                for (int r = 0; r < 4; ++r) {
                    float xsv = (kk == 0) ? xv[r].x : (kk == 1) ? xv[r].y
                              : (kk == 2) ? xv[r].z : xv[r].w;
                    xx[r] = dup2(xsv);
                }
                const ulonglong2* wr = reinterpret_cast<const ulonglong2*>(
                    wb + (k4 + kk) * OUT + ci * CP);
                #pragma unroll
                for (int q = 0; q < NP / 2; ++q) {
                    ulonglong2 w2 = wr[q];
                    #pragma unroll
                    for (int r = 0; r < 4; ++r) {
                        ffma2(acc[r][2 * q],     xx[r], w2.x);
                        ffma2(acc[r][2 * q + 1], xx[r], w2.y);
                    }
                }
            }
        }
    }

    #pragma unroll
    for (int j = 0; j < NP; ++j) {
        float b0 = __ldg(bias + ci * CP + 2 * j);
        float b1 = __ldg(bias + ci * CP + 2 * j + 1);
        #pragma unroll
        for (int r = 0; r < 4; ++r) {
            float2 p = *reinterpret_cast<float2*>(&acc[r][j]);
            float v0 = p.x + b0, v1 = p.y + b1;
            if (ACT) { v0 = fmaxf(v0, 0.f); v1 = fmaxf(v1, 0.f); }
            const int row = pi * 4 + r;
            ys[(size_t)row * yp + ci * CP + 2 * j]     = v0;
            ys[(size_t)row * yp + ci * CP + 2 * j + 1] = v1;
        }
    }
}

// ---------------- fused main kernel: one block = two rays ----------------
__global__ void __launch_bounds__(NTHREADS, 1)
voxelmlp_main(const float* __restrict__ ray_pts,
              const float* __restrict__ viewdirs,
              const float* __restrict__ density,
              const float* __restrict__ dt_w0, const float* __restrict__ dt_b0,
              const float* __restrict__ dt_w1, const float* __restrict__ dt_b1,
              const float* __restrict__ dt_wo, const float* __restrict__ dt_bo,
              const float* __restrict__ fn_w0, const float* __restrict__ fn_b0,
              const float* __restrict__ dec_wf, const float* __restrict__ dec_bf,
              const float* __restrict__ dec_w0, const float* __restrict__ dec_b0,
              const float* __restrict__ dec_w1, const float* __restrict__ dec_b1,
              float* __restrict__ out) {
    extern __shared__ float sm[];
    float* A     = sm + OFF_A;     // [128][212]
    float* Bb    = sm + OFF_B;     // [128][132]
    float* WS    = sm + OFF_WS;    // [3][16][128]
    float* W3    = sm + OFF_W3;
    float* W3B   = sm + OFF_W3B;
    float* PD    = sm + OFF_PD;    // [128][3]
    float* ALP   = sm + OFF_ALP;   // [128]
    float* WGT   = sm + OFF_WGT;   // [128]
    float* RGB   = sm + OFF_RGB;   // [128][3]
    float* VE    = sm + OFF_VE;    // [2][21] (+pad)
    float* ALAST = sm + OFF_ALAST; // [2]
    int*   TI    = reinterpret_cast<int*>(sm + OFF_TI);   // [128][3]
    float* TFR   = sm + OFF_TFR;                          // [128][3]
    uint32_t mb[NBUF];
    mb[0] = smem_u32(sm + OFF_MB);
    mb[1] = mb[0] + 8;
    mb[2] = mb[0] + 16;

    const int tid   = threadIdx.x;
    const int gbase = blockIdx.x * NPTS;     // first point of this block
    const int ray0  = blockIdx.x * 2;
    int ph[NBUF] = {0, 0, 0};

    // ---- init: zero weight buffers (0*Inf guard on first partial tiles) ----
    for (int i = tid; i < NBUF * KT * 128; i += NTHREADS) WS[i] = 0.f;
    if (tid == 0) { mbar_init(mb[0], 1); mbar_init(mb[1], 1); mbar_init(mb[2], 1); }
    asm volatile("fence.proxy.async.shared::cta;" ::: "memory");

    // stage small weights to smem
    for (int i = tid; i < 128 * 3; i += NTHREADS) W3[i] = __ldg(dt_wo + i);
    if (tid < 3) W3[384 + tid] = __ldg(dt_bo + tid);
    for (int i = tid; i < 64 * 3; i += NTHREADS) W3B[i] = __ldg(dec_w1 + i);
    if (tid < 3) W3B[192 + tid] = __ldg(dec_b1 + tid);

    // ---- phase 0: deform input X = [pts_emb(27), tf(60)], pad -> 96 ----
    if (tid < NPTS) {
        const int p = tid;
        float* row = A + p * AP;
        #pragma unroll
        for (int d = 0; d < 3; ++d) {
            float v = ray_pts[(size_t)(gbase + p) * 3 + d];
            row[d] = v;
            float s, c;
            __sincosf(v, &s, &c);
            row[3 + d * 4]  = s;
            row[15 + d * 4] = c;
            #pragma unroll
            for (int k = 1; k < 4; ++k) {
                float s2 = 2.f * s * c;
                float c2 = fmaf(-2.f * s, s, 1.f);
                s = s2; c = c2;
                row[3 + d * 4 + k]  = s;
                row[15 + d * 4 + k] = c;
            }
        }
    }
    if (tid >= NPTS && tid < NPTS + 6) {  // view embedding, 2 rays
        const int j = tid - NPTS;
        const int r = j / 3, d = j % 3;
        float v = viewdirs[(size_t)(ray0 + r) * 3 + d];
        float* ve = VE + r * 21;
        ve[d] = v;
        float s, c;
        __sincosf(v, &s, &c);
        ve[3 + d * 3]  = s;
        ve[12 + d * 3] = c;
        #pragma unroll
        for (int k = 1; k < 3; ++k) {
            float s2 = 2.f * s * c;
            float c2 = fmaf(-2.f * s, s, 1.f);
            s = s2; c = c2;
            ve[3 + d * 3 + k]  = s;
            ve[12 + d * 3 + k] = c;
        }
    }
    for (int i = tid; i < NPTS * 60; i += NTHREADS) {
        int p = i & (NPTS - 1), j = i >> 7;
        A[p * AP + 27 + j] = g_tf[j];
    }
    for (int i = tid; i < NPTS * 9; i += NTHREADS) {
        int p = i & (NPTS - 1), j = i >> 7;
        A[p * AP + 87 + j] = 0.f;
    }
    __syncthreads();

    // ---- deformation net ----
    mlp_layer<128, 1>(dt_w0, dt_b0, A, AP, 87, 96, Bb, BP, WS, mb, ph, tid);
    __syncthreads();
    mlp_layer<128, 1>(dt_w1, dt_b1, Bb, BP, 128, 128, A, AP, WS, mb, ph, tid);
    __syncthreads();

    {   // dx = H @ dt_wo + dt_bo (quad-parallel, weights from smem)
        const int p  = tid >> 2;
        const int l4 = tid & 3;
        float d0 = 0.f, d1 = 0.f, d2 = 0.f;
        const float* row = A + p * AP;
        #pragma unroll 8
        for (int k = l4; k < 128; k += 4) {
            float h = row[k];
            d0 = fmaf(h, W3[k * 3 + 0], d0);
            d1 = fmaf(h, W3[k * 3 + 1], d1);
            d2 = fmaf(h, W3[k * 3 + 2], d2);
        }
        d0 += __shfl_xor_sync(0xffffffffu, d0, 1);
        d0 += __shfl_xor_sync(0xffffffffu, d0, 2);
        d1 += __shfl_xor_sync(0xffffffffu, d1, 1);
        d1 += __shfl_xor_sync(0xffffffffu, d1, 2);
        d2 += __shfl_xor_sync(0xffffffffu, d2, 1);
        d2 += __shfl_xor_sync(0xffffffffu, d2, 2);
        if (l4 == 0) {
            PD[p * 3 + 0] = ray_pts[(size_t)(gbase + p) * 3 + 0] + d0 + W3[384];
            PD[p * 3 + 1] = ray_pts[(size_t)(gbase + p) * 3 + 1] + d1 + W3[385];
            PD[p * 3 + 2] = ray_pts[(size_t)(gbase + p) * 3 + 2] + d2 + W3[386];
        }
    }
    __syncthreads();

    // ---- density -> alpha ----
    if (tid < NPTS) {
        const int p = tid;
        int ii[3]; float ff[3];
        tri_setup(PD + p * 3, GRID_C, ii, ff);
        float dens = tri_gather1(density, GRID_C, ii[0], ii[1], ii[2],
                                 ff[0], ff[1], ff[2]);
        float x = dens + ACT_SHIFT_C;
        float sp = (x > 20.f) ? x : log1pf(__expf(x));
        ALP[p] = 1.f - __expf(-sp * 0.5f);
    }
    __syncthreads();
    if (tid < 2) {  // per-ray exclusive cumprod (2 rays)
        float T = 1.f;
        const int base = tid * PPR_C;
        for (int i = 0; i < PPR_C; ++i) {
            float a = ALP[base + i];
            WGT[base + i] = a * T;
            T *= (1.f - a);
        }
        ALAST[tid] = T;
    }

    // ---- 3-scale feature trilerp (transposed grids, float4 gathers) ----
    #pragma unroll 1
    for (int s = 0; s < 3; ++s) {
        const int D = GRID_C >> s;
        if (tid < NPTS) {
            int ii[3]; float ff[3];
            tri_setup(PD + tid * 3, D, ii, ff);
            TI[tid * 3 + 0] = ii[0]; TI[tid * 3 + 1] = ii[1]; TI[tid * 3 + 2] = ii[2];
            TFR[tid * 3 + 0] = ff[0]; TFR[tid * 3 + 1] = ff[1]; TFR[tid * 3 + 2] = ff[2];
        }
        __syncthreads();
        const float* gp = (s == 0) ? (const float*)g_feat_t
                        : (s == 1) ? (const float*)g_pool2t
                                   : (const float*)g_pool4t;
        {
            const int p = tid >> 2, q = tid & 3;
            if (q < 3) {
                int ix = TI[p * 3 + 0], iy = TI[p * 3 + 1], iz = TI[p * 3 + 2];
                float fx = TFR[p * 3 + 0], fy = TFR[p * 3 + 1], fz = TFR[p * 3 + 2];
                const size_t sy = (size_t)D * VD_C;
                const size_t sx = (size_t)D * sy;
                const float* b = gp + (size_t)ix * sx + (size_t)iy * sy
                               + (size_t)iz * VD_C + q * 4;
                float4 v000 = __ldg((const float4*)(b));
                float4 v001 = __ldg((const float4*)(b + VD_C));
                float4 v010 = __ldg((const float4*)(b + sy));
                float4 v011 = __ldg((const float4*)(b + sy + VD_C));
                float4 v100 = __ldg((const float4*)(b + sx));
                float4 v101 = __ldg((const float4*)(b + sx + VD_C));
                float4 v110 = __ldg((const float4*)(b + sx + sy));
                float4 v111 = __ldg((const float4*)(b + sx + sy + VD_C));
                float4 c00 = lerp4(v000, v001, fz);
                float4 c01 = lerp4(v010, v011, fz);
                float4 c10 = lerp4(v100, v101, fz);
                float4 c11 = lerp4(v110, v111, fz);
                float4 c0 = lerp4(c00, c01, fy);
                float4 c1 = lerp4(c10, c11, fy);
                float4 r  = lerp4(c0, c1, fx);
                *reinterpret_cast<float4*>(A + p * AP + s * 12 + q * 4) = r;
            }
        }
        __syncthreads();
    }

    // ---- featurenet input: sin_emb(feat,2)(180) + sin_emb(pts_d,4)(27) ----
    for (int i = tid; i < NPTS * 36; i += NTHREADS) {
        int p = i & (NPTS - 1), d = i >> 7;
        float* row = A + p * AP;
        float f = row[d];
        float s1, c1;
        __sincosf(f, &s1, &c1);
        float s2 = 2.f * s1 * c1;
        float c2 = fmaf(-2.f * s1, s1, 1.f);
        row[36 + 2 * d]  = s1;  row[37 + 2 * d]  = s2;
        row[108 + 2 * d] = c1;  row[109 + 2 * d] = c2;
    }
    if (tid < NPTS) {
        const int p = tid;
        float* row = A + p * AP;
        #pragma unroll
        for (int d = 0; d < 3; ++d) {
            float v = PD[p * 3 + d];
            row[180 + d] = v;
            float s, c;
            __sincosf(v, &s, &c);
            row[183 + d * 4] = s;
            row[195 + d * 4] = c;
            #pragma unroll
            for (int k = 1; k < 4; ++k) {
                float s2 = 2.f * s * c;
                float c2 = fmaf(-2.f * s, s, 1.f);
                s = s2; c = c2;
                row[183 + d * 4 + k] = s;
                row[195 + d * 4 + k] = c;
            }
        }
        row[207] = 0.f;
    }
    __syncthreads();

    // ---- featurenet + decoder ----
    mlp_layer<128, 1>(fn_w0, fn_b0, A, AP, 207, 208, Bb, BP, WS, mb, ph, tid);
    __syncthreads();
    mlp_layer<128, 0>(dec_wf, dec_bf, Bb, BP, 128, 128, A, AP, WS, mb, ph, tid);
    __syncthreads();
    if (tid < NPTS) {  // append vemb of the point's ray; pad to 160
        float* row = A + tid * AP;
        const float* ve = VE + (tid >> 6) * 21;
        #pragma unroll
        for (int j = 0; j < 21; ++j) row[128 + j] = ve[j];
        #pragma unroll
        for (int j = 149; j < 160; ++j) row[j] = 0.f;
    }
    __syncthreads();
    mlp_layer<64, 1>(dec_w0, dec_b0, A, AP, 149, 160, Bb, BP, WS, mb, ph, tid);
    __syncthreads();

    {   // final 64->3 + sigmoid (quad-parallel, weights from smem)
        const int p  = tid >> 2;
        const int l4 = tid & 3;
        float r0 = 0.f, r1 = 0.f, r2 = 0.f;
        const float* row = Bb + p * BP;
        #pragma unroll 4
        for (int k = l4; k < 64; k += 4) {
            float h = row[k];
            r0 = fmaf(h, W3B[k * 3 + 0], r0);
            r1 = fmaf(h, W3B[k * 3 + 1], r1);
            r2 = fmaf(h, W3B[k * 3 + 2], r2);
        }
        r0 += __shfl_xor_sync(0xffffffffu, r0, 1);
        r0 += __shfl_xor_sync(0xffffffffu, r0, 2);
        r1 += __shfl_xor_sync(0xffffffffu, r1, 1);
        r1 += __shfl_xor_sync(0xffffffffu, r1, 2);
        r2 += __shfl_xor_sync(0xffffffffu, r2, 1);
        r2 += __shfl_xor_sync(0xffffffffu, r2, 2);
        if (l4 == 0) {
            r0 += W3B[192]; r1 += W3B[193]; r2 += W3B[194];
            RGB[p * 3 + 0] = 1.f / (1.f + __expf(-r0));
            RGB[p * 3 + 1] = 1.f / (1.f + __expf(-r1));
            RGB[p * 3 + 2] = 1.f / (1.f + __expf(-r2));
        }
    }
    __syncthreads();

    if (tid < 6) {  // composite with white background (2 rays x 3 channels)
        const int r = tid / 3, ch = tid % 3;
        float s = ALAST[r];
        const int base = r * PPR_C;
        for (int p = 0; p < PPR_C; ++p)
            s = fmaf(WGT[base + p], RGB[(base + p) * 3 + ch], s);
        out[(size_t)(ray0 + r) * 3 + ch] = s;
    }
}

// ---------------- launch ----------------
extern "C" void kernel_launch(void* const* d_in, const int* in_sizes, int n_in,
                              void* d_out, int out_size) {
    (void)in_sizes; (void)n_in; (void)out_size;
    const float* ray_pts    = (const float*)d_in[0];
    const float* viewdirs   = (const float*)d_in[1];
    const float* frame_time = (const float*)d_in[2];
    const float* feature    = (const float*)d_in[3];
    const float* density    = (const float*)d_in[4];
    const float* tn_w0 = (const float*)d_in[5];
    const float* tn_b0 = (const float*)d_in[6];
    const float* tn_w1 = (const float*)d_in[7];
    const float* tn_b1 = (const float*)d_in[8];
    const float* dt_w0 = (const float*)d_in[9];
    const float* dt_b0 = (const float*)d_in[10];
    const float* dt_w1 = (const float*)d_in[11];
    const float* dt_b1 = (const float*)d_in[12];
    const float* dt_wo = (const float*)d_in[13];
    const float* dt_bo = (const float*)d_in[14];
    const float* fn_w0 = (const float*)d_in[15];
    const float* fn_b0 = (const float*)d_in[16];
    const float* dec_wf = (const float*)d_in[17];
    const float* dec_bf = (const float*)d_in[18];
    const float* dec_w0 = (const float*)d_in[19];
    const float* dec_b0 = (const float*)d_in[20];
    const float* dec_w1 = (const float*)d_in[21];
    const float* dec_b1 = (const float*)d_in[22];
    float* out = (float*)d_out;

    cudaFuncSetAttribute(voxelmlp_main, cudaFuncAttributeMaxDynamicSharedMemorySize,
                         SMEM_BYTES);

    {
        const int V = GRID_C * GRID_C * GRID_C;
        transpose_feat<<<(V + 255) / 256, 256>>>(feature);
    }
    pool2t_kernel<<<(64 * 64 * 64 + 255) / 256, 256>>>();
    pool4t_kernel<<<(32 * 32 * 32 + 255) / 256, 256>>>();
    timenet_kernel<<<1, 128>>>(frame_time, tn_w0, tn_b0, tn_w1, tn_b1);

    voxelmlp_main<<<NBLOCKS, NTHREADS, SMEM_BYTES>>>(
        ray_pts, viewdirs, density,
        dt_w0, dt_b0, dt_w1, dt_b1, dt_wo, dt_bo,
        fn_w0, fn_b0, dec_wf, dec_bf,
        dec_w0, dec_b0, dec_w1, dec_b1,
        out);
}

// round 15
// speedup vs baseline: 1.5626x; 1.5626x over previous
#include <cuda_runtime.h>
#include <cstdint>
#include <math.h>

// ---------------- problem constants ----------------
#define N_RAYS_C   4096
#define PPR_C      64
#define VD_C       12
#define GRID_C     128
#define ACT_SHIFT_C (-4.5951199f)   // log(1/(1-0.01) - 1)

#define AP 208
#define BP 128
#define KT 16
#define NTHREADS 256

// ---- smem layout (floats) ----
#define OFF_A     0
#define OFF_B     (64*AP)                    // 13312
#define OFF_WS    (OFF_B + 64*BP)            // 21504
#define OFF_W3    (OFF_WS + 2*KT*128)        // 25600 (dt_wo 384 + bias 3)
#define OFF_W3B   (OFF_W3 + 388)             // dec_w1 192 + bias 3
#define OFF_PD    (OFF_W3B + 196)
#define OFF_ALP   (OFF_PD + 192)
#define OFF_WGT   (OFF_ALP + 64)
#define OFF_RGB   (OFF_WGT + 64)
#define OFF_VE    (OFF_RGB + 192)
#define OFF_ALAST (OFF_VE + 24)
#define OFF_TI    (OFF_ALAST + 8)
#define OFF_TFR   (OFF_TI + 192)
#define OFF_MB    (OFF_TFR + 192)            // 2 x u64 mbarriers
#define SMEM_FLOATS (OFF_MB + 4)
#define SMEM_BYTES  (SMEM_FLOATS * 4)

// ---------------- device scratch (static: no allocation) ----------------
__device__ float g_feat_t[(size_t)GRID_C * GRID_C * GRID_C * VD_C];  // [X,Y,Z,C]
__device__ float g_pool2t[(size_t)64 * 64 * 64 * VD_C];
__device__ float g_pool4t[(size_t)32 * 32 * 32 * VD_C];
__device__ float g_tf[64];   // 60 used

// ---------------- f32x2 / ptx helpers ----------------
__device__ __forceinline__ void ffma2(unsigned long long& d, unsigned long long a,
                                      unsigned long long b) {
    asm("fma.rn.f32x2 %0, %1, %2, %0;" : "+l"(d) : "l"(a), "l"(b));
}
__device__ __forceinline__ unsigned long long dup2(float x) {
    unsigned long long r;
    asm("mov.b64 %0, {%1, %1};" : "=l"(r) : "f"(x));
    return r;
}
__device__ __forceinline__ uint32_t smem_u32(const void* p) {
    return (uint32_t)__cvta_generic_to_shared(p);
}
__device__ __forceinline__ void mbar_init(uint32_t a, uint32_t cnt) {
    asm volatile("mbarrier.init.shared.b64 [%0], %1;" :: "r"(a), "r"(cnt) : "memory");
}
__device__ __forceinline__ void mbar_expect(uint32_t a, uint32_t bytes) {
    asm volatile("mbarrier.arrive.expect_tx.shared.b64 _, [%0], %1;"
                 :: "r"(a), "r"(bytes) : "memory");
}
__device__ __forceinline__ void mbar_wait(uint32_t a, uint32_t parity) {
    asm volatile(
        "{\n\t"
        ".reg .pred P;\n"
        "LW%=:\n\t"
        "mbarrier.try_wait.parity.acquire.cta.shared::cta.b64 P, [%0], %1;\n\t"
        "@!P bra LW%=;\n\t"
        "}"
        :: "r"(a), "r"(parity) : "memory");
}
__device__ __forceinline__ void bulk_g2s(uint32_t dst, const float* src,
                                         uint32_t bytes, uint32_t mbar) {
    asm volatile(
        "cp.async.bulk.shared::cluster.global.mbarrier::complete_tx::bytes "
        "[%0], [%1], %2, [%3];"
        :: "r"(dst), "l"(src), "r"(bytes), "r"(mbar) : "memory");
}

// ---------------- grid transpose + pooling (transposed layouts) ----------------
__global__ void transpose_feat(const float* __restrict__ f) {
    int v = blockIdx.x * blockDim.x + threadIdx.x;
    const int V = GRID_C * GRID_C * GRID_C;
    if (v >= V) return;
    float vals[VD_C];
    #pragma unroll
    for (int c = 0; c < VD_C; ++c) vals[c] = __ldg(f + (size_t)c * V + v);
    float* dst = g_feat_t + (size_t)v * VD_C;
    #pragma unroll
    for (int q = 0; q < 3; ++q)
        *reinterpret_cast<float4*>(dst + q * 4) =
            make_float4(vals[q * 4], vals[q * 4 + 1], vals[q * 4 + 2], vals[q * 4 + 3]);
}

__global__ void pool2t_kernel() {
    int v = blockIdx.x * blockDim.x + threadIdx.x;
    if (v >= 64 * 64 * 64) return;
    int z = v & 63, y = (v >> 6) & 63, x = v >> 12;
    float acc[VD_C];
    #pragma unroll
    for (int c = 0; c < VD_C; ++c) acc[c] = 0.f;
    #pragma unroll
    for (int d = 0; d < 8; ++d) {
        int dx = d >> 2, dy = (d >> 1) & 1, dz = d & 1;
        const float* s = g_feat_t +
            ((((size_t)(2 * x + dx) * 128 + (2 * y + dy)) * 128 + (2 * z + dz)) * VD_C);
        #pragma unroll
        for (int q = 0; q < 3; ++q) {
            float4 b = *reinterpret_cast<const float4*>(s + q * 4);
            acc[q * 4 + 0] += b.x; acc[q * 4 + 1] += b.y;
            acc[q * 4 + 2] += b.z; acc[q * 4 + 3] += b.w;
        }
    }
    float* dst = g_pool2t + (size_t)v * VD_C;
    #pragma unroll
    for (int q = 0; q < 3; ++q)
        *reinterpret_cast<float4*>(dst + q * 4) =
            make_float4(acc[q * 4] * 0.125f, acc[q * 4 + 1] * 0.125f,
                        acc[q * 4 + 2] * 0.125f, acc[q * 4 + 3] * 0.125f);
}

__global__ void pool4t_kernel() {
    int v = blockIdx.x * blockDim.x + threadIdx.x;
    if (v >= 32 * 32 * 32) return;
    int z = v & 31, y = (v >> 5) & 31, x = v >> 10;
    float acc[VD_C];
    #pragma unroll
    for (int c = 0; c < VD_C; ++c) acc[c] = 0.f;
    #pragma unroll
    for (int d = 0; d < 8; ++d) {
        int dx = d >> 2, dy = (d >> 1) & 1, dz = d & 1;
        const float* s = g_pool2t +
            ((((size_t)(2 * x + dx) * 64 + (2 * y + dy)) * 64 + (2 * z + dz)) * VD_C);
        #pragma unroll
        for (int q = 0; q < 3; ++q) {
            float4 b = *reinterpret_cast<const float4*>(s + q * 4);
            acc[q * 4 + 0] += b.x; acc[q * 4 + 1] += b.y;
            acc[q * 4 + 2] += b.z; acc[q * 4 + 3] += b.w;
        }
    }
    float* dst = g_pool4t + (size_t)v * VD_C;
    #pragma unroll
    for (int q = 0; q < 3; ++q)
        *reinterpret_cast<float4*>(dst + q * 4) =
            make_float4(acc[q * 4] * 0.125f, acc[q * 4 + 1] * 0.125f,
                        acc[q * 4 + 2] * 0.125f, acc[q * 4 + 3] * 0.125f);
}

// ---------------- timenet (tiny, runs once) ----------------
__global__ void timenet_kernel(const float* __restrict__ ft,
                               const float* __restrict__ w0, const float* __restrict__ b0,
                               const float* __restrict__ w1, const float* __restrict__ b1) {
    __shared__ float temb[9];
    __shared__ float h[128];
    int tid = threadIdx.x;
    if (tid == 0) {
        float t = ft[0];
        temb[0] = t;
        #pragma unroll
        for (int k = 0; k < 4; ++k) {
            temb[1 + k] = sinf(t * (float)(1 << k));
            temb[5 + k] = cosf(t * (float)(1 << k));
        }
    }
    __syncthreads();
    {
        float v = b0[tid];
        #pragma unroll
        for (int k = 0; k < 9; ++k) v = fmaf(temb[k], w0[k * 128 + tid], v);
        h[tid] = fmaxf(v, 0.f);
    }
    __syncthreads();
    if (tid < 60) {
        float v = b1[tid];
        for (int k = 0; k < 128; ++k) v = fmaf(h[k], w1[k * 60 + tid], v);
        g_tf[tid] = v;
    }
}

// ---------------- trilerp setup ----------------
__device__ __forceinline__ void tri_setup(const float* pd, int D, int* ii, float* ff) {
    float dim = (float)(D - 1);
    float hi = dim - 1e-4f;
    #pragma unroll
    for (int c = 0; c < 3; ++c) {
        float t = (pd[c] + 1.f) * 0.5f * dim;
        t = fminf(fmaxf(t, 0.f), hi);
        float fl = floorf(t);
        ii[c] = (int)fl;
        ff[c] = t - fl;
    }
}

__device__ __forceinline__ float tri_gather1(const float* __restrict__ g, int D,
                                             int ix, int iy, int iz,
                                             float fx, float fy, float fz) {
    size_t sx = (size_t)D * D;
    int sy = D;
    const float* b = g + (size_t)ix * sx + (size_t)iy * sy + iz;
    float v000 = __ldg(b),            v001 = __ldg(b + 1);
    float v010 = __ldg(b + sy),       v011 = __ldg(b + sy + 1);
    float v100 = __ldg(b + sx),       v101 = __ldg(b + sx + 1);
    float v110 = __ldg(b + sx + sy),  v111 = __ldg(b + sx + sy + 1);
    float c00 = v000 + (v001 - v000) * fz;
    float c01 = v010 + (v011 - v010) * fz;
    float c10 = v100 + (v101 - v100) * fz;
    float c11 = v110 + (v111 - v110) * fz;
    float c0 = c00 + (c01 - c00) * fy;
    float c1 = c10 + (c11 - c10) * fy;
    return c0 + (c1 - c0) * fx;
}

__device__ __forceinline__ float4 lerp4(float4 a, float4 b, float t) {
    return make_float4(a.x + (b.x - a.x) * t, a.y + (b.y - a.y) * t,
                       a.z + (b.z - a.z) * t, a.w + (b.w - a.w) * t);
}

// ---------------- register-tiled f32x2 GEMM, TMA double buffer --------------
// 64 points x OUT cols; 256 threads: ci = tid&31 (CP cols), pi = tid>>5 (8 pts)
// 8-row blocking: one weight LDS.128 feeds 8 rows -> smem traffic halved vs 4-row.
template <int OUT, int ACT>
__device__ __forceinline__ void mlp_layer(
    const float* __restrict__ W, const float* __restrict__ bias,
    const float* __restrict__ xs, int xp, int INA, int INP,
    float* __restrict__ ys, int yp,
    float* __restrict__ ws, uint32_t mb0, uint32_t mb1,
    int& ph0, int& ph1, int tid) {
    constexpr int CP = OUT / 32;   // 4 (OUT=128) or 2 (OUT=64) cols per thread
    constexpr int NP = CP / 2;     // f32x2 pairs
    const int ci = tid & 31;
    const int pi = tid >> 5;       // 8 groups x 8 rows
    unsigned long long acc[8][NP];
    #pragma unroll
    for (int r = 0; r < 8; ++r)
        #pragma unroll
        for (int j = 0; j < NP; ++j) acc[r][j] = 0ull;

    const int ntiles = INP / KT;

    auto issue = [&](int t, int buf) {
        if (tid == 0) {
            int rows = INA - t * KT; if (rows > KT) rows = KT;
            uint32_t bytes = (uint32_t)rows * OUT * 4u;
            uint32_t mb = buf ? mb1 : mb0;
            mbar_expect(mb, bytes);
            bulk_g2s(smem_u32(ws + buf * (KT * 128)), W + (size_t)t * KT * OUT,
                     bytes, mb);
        }
    };

    issue(0, 0);
    for (int t = 0; t < ntiles; ++t) {
        const int buf = t & 1;
        if (buf == 0) { mbar_wait(mb0, (uint32_t)ph0); ph0 ^= 1; }
        else          { mbar_wait(mb1, (uint32_t)ph1); ph1 ^= 1; }
        __syncthreads();                       // all threads past previous tile
        if (t + 1 < ntiles) issue(t + 1, buf ^ 1);

        const float* xb = xs + (size_t)(pi * 8) * xp + t * KT;
        const float* wb = ws + buf * (KT * 128);
        #pragma unroll
        for (int k4 = 0; k4 < KT; k4 += 4) {
            float4 xv[8];
            #pragma unroll
            for (int r = 0; r < 8; ++r)
                xv[r] = *reinterpret_cast<const float4*>(xb + r * xp + k4);
            #pragma unroll
            for (int kk = 0; kk < 4; ++kk) {
                unsigned long long xx[8];
                #pragma unroll
                for (int r = 0; r < 8; ++r) {
                    float xsv = (kk == 0) ? xv[r].x : (kk == 1) ? xv[r].y
                              : (kk == 2) ? xv[r].z : xv[r].w;
                    xx[r] = dup2(xsv);
                }
                const float* wr = wb + (k4 + kk) * OUT + ci * CP;
                if (CP == 4) {
                    ulonglong2 w2 = *reinterpret_cast<const ulonglong2*>(wr);
                    #pragma unroll
                    for (int r = 0; r < 8; ++r) {
                        ffma2(acc[r][0], xx[r], w2.x);
                        ffma2(acc[r][NP - 1], xx[r], w2.y);  // NP=2 -> acc[r][1]
                    }
                } else {
                    unsigned long long w1 = *reinterpret_cast<const unsigned long long*>(wr);
                    #pragma unroll
                    for (int r = 0; r < 8; ++r) ffma2(acc[r][0], xx[r], w1);
                }
            }
        }
    }

    #pragma unroll
    for (int j = 0; j < NP; ++j) {
        float b0 = __ldg(bias + ci * CP + 2 * j);
        float b1 = __ldg(bias + ci * CP + 2 * j + 1);
        #pragma unroll
        for (int r = 0; r < 8; ++r) {
            float2 p = *reinterpret_cast<float2*>(&acc[r][j]);
            float v0 = p.x + b0, v1 = p.y + b1;
            if (ACT) { v0 = fmaxf(v0, 0.f); v1 = fmaxf(v1, 0.f); }
            const int row = pi * 8 + r;
            *reinterpret_cast<float2*>(ys + (size_t)row * yp + ci * CP + 2 * j) =
                make_float2(v0, v1);
        }
    }
}

// ---------------- fused main kernel: one block = one ray ----------------
__global__ void __launch_bounds__(NTHREADS, 2)
voxelmlp_main(const float* __restrict__ ray_pts,
              const float* __restrict__ viewdirs,
              const float* __restrict__ density,
              const float* __restrict__ dt_w0, const float* __restrict__ dt_b0,
              const float* __restrict__ dt_w1, const float* __restrict__ dt_b1,
              const float* __restrict__ dt_wo, const float* __restrict__ dt_bo,
              const float* __restrict__ fn_w0, const float* __restrict__ fn_b0,
              const float* __restrict__ dec_wf, const float* __restrict__ dec_bf,
              const float* __restrict__ dec_w0, const float* __restrict__ dec_b0,
              const float* __restrict__ dec_w1, const float* __restrict__ dec_b1,
              float* __restrict__ out) {
    extern __shared__ float sm[];
    float* A     = sm + OFF_A;     // [64][208]
    float* Bb    = sm + OFF_B;     // [64][128]
    float* WS    = sm + OFF_WS;    // [2][16][128]
    float* W3    = sm + OFF_W3;
    float* W3B   = sm + OFF_W3B;
    float* PD    = sm + OFF_PD;
    float* ALP   = sm + OFF_ALP;
    float* WGT   = sm + OFF_WGT;
    float* RGB   = sm + OFF_RGB;
    float* VE    = sm + OFF_VE;
    float* ALAST = sm + OFF_ALAST;
    int*   TI    = reinterpret_cast<int*>(sm + OFF_TI);
    float* TFR   = sm + OFF_TFR;
    const uint32_t mb0 = smem_u32(sm + OFF_MB);
    const uint32_t mb1 = mb0 + 8;

    const int tid   = threadIdx.x;
    const int ray   = blockIdx.x;
    const int gbase = ray * PPR_C;
    int ph0 = 0, ph1 = 0;

    // ---- init: zero weight buffers (0*Inf guard on padded rows) ----
    for (int i = tid; i < 2 * KT * 128; i += NTHREADS) WS[i] = 0.f;
    if (tid == 0) { mbar_init(mb0, 1); mbar_init(mb1, 1); }
    asm volatile("fence.proxy.async.shared::cta;" ::: "memory");

    // stage small weights to smem
    for (int i = tid; i < 128 * 3; i += NTHREADS) W3[i] = __ldg(dt_wo + i);
    if (tid < 3) W3[384 + tid] = __ldg(dt_bo + tid);
    for (int i = tid; i < 64 * 3; i += NTHREADS) W3B[i] = __ldg(dec_w1 + i);
    if (tid < 3) W3B[192 + tid] = __ldg(dec_b1 + tid);

    // ---- phase 0: deform input X = [pts_emb(27), tf(60)], pad -> 96 ----
    if (tid < 64) {
        const int p = tid;
        float* row = A + p * AP;
        #pragma unroll
        for (int d = 0; d < 3; ++d) {
            float v = ray_pts[(size_t)(gbase + p) * 3 + d];
            row[d] = v;
            float s, c;
            __sincosf(v, &s, &c);
            row[3 + d * 4]  = s;
            row[15 + d * 4] = c;
            #pragma unroll
            for (int k = 1; k < 4; ++k) {
                float s2 = 2.f * s * c;
                float c2 = fmaf(-2.f * s, s, 1.f);
                s = s2; c = c2;
                row[3 + d * 4 + k]  = s;
                row[15 + d * 4 + k] = c;
            }
        }
    }
    if (tid >= 64 && tid < 67) {  // view embedding
        const int d = tid - 64;
        float v = viewdirs[(size_t)ray * 3 + d];
        VE[d] = v;
        float s, c;
        __sincosf(v, &s, &c);
        VE[3 + d * 3]  = s;
        VE[12 + d * 3] = c;
        #pragma unroll
        for (int k = 1; k < 3; ++k) {
            float s2 = 2.f * s * c;
            float c2 = fmaf(-2.f * s, s, 1.f);
            s = s2; c = c2;
            VE[3 + d * 3 + k]  = s;
            VE[12 + d * 3 + k] = c;
        }
    }
    for (int i = tid; i < 64 * 60; i += NTHREADS) {
        int p = i & 63, j = i >> 6;
        A[p * AP + 27 + j] = g_tf[j];
    }
    for (int i = tid; i < 64 * 9; i += NTHREADS) {
        int p = i & 63, j = i >> 6;
        A[p * AP + 87 + j] = 0.f;
    }
    __syncthreads();

    // ---- deformation net ----
    mlp_layer<128, 1>(dt_w0, dt_b0, A, AP, 87, 96, Bb, BP, WS, mb0, mb1, ph0, ph1, tid);
    __syncthreads();
    mlp_layer<128, 1>(dt_w1, dt_b1, Bb, BP, 128, 128, A, AP, WS, mb0, mb1, ph0, ph1, tid);
    __syncthreads();

    {   // dx = H @ dt_wo + dt_bo (quad-parallel, weights from smem)
        const int p  = tid >> 2;
        const int l4 = tid & 3;
        float d0 = 0.f, d1 = 0.f, d2 = 0.f;
        const float* row = A + p * AP;
        #pragma unroll 8
        for (int k = l4; k < 128; k += 4) {
            float h = row[k];
            d0 = fmaf(h, W3[k * 3 + 0], d0);
            d1 = fmaf(h, W3[k * 3 + 1], d1);
            d2 = fmaf(h, W3[k * 3 + 2], d2);
        }
        d0 += __shfl_xor_sync(0xffffffffu, d0, 1);
        d0 += __shfl_xor_sync(0xffffffffu, d0, 2);
        d1 += __shfl_xor_sync(0xffffffffu, d1, 1);
        d1 += __shfl_xor_sync(0xffffffffu, d1, 2);
        d2 += __shfl_xor_sync(0xffffffffu, d2, 1);
        d2 += __shfl_xor_sync(0xffffffffu, d2, 2);
        if (l4 == 0) {
            PD[p * 3 + 0] = ray_pts[(size_t)(gbase + p) * 3 + 0] + d0 + W3[384];
            PD[p * 3 + 1] = ray_pts[(size_t)(gbase + p) * 3 + 1] + d1 + W3[385];
            PD[p * 3 + 2] = ray_pts[(size_t)(gbase + p) * 3 + 2] + d2 + W3[386];
        }
    }
    __syncthreads();

    // ---- density -> alpha ----
    if (tid < 64) {
        const int p = tid;
        int ii[3]; float ff[3];
        tri_setup(PD + p * 3, GRID_C, ii, ff);
        float dens = tri_gather1(density, GRID_C, ii[0], ii[1], ii[2],
                                 ff[0], ff[1], ff[2]);
        float x = dens + ACT_SHIFT_C;
        float sp = (x > 20.f) ? x : log1pf(__expf(x));
        ALP[p] = 1.f - __expf(-sp * 0.5f);
    }
    __syncthreads();
    if (tid == 0) {  // per-ray exclusive cumprod
        float T = 1.f;
        for (int i = 0; i < PPR_C; ++i) {
            float a = ALP[i];
            WGT[i] = a * T;
            T *= (1.f - a);
        }
        ALAST[0] = T;
    }

    // ---- 3-scale feature trilerp (transposed grids, float4 gathers) ----
    #pragma unroll 1
    for (int s = 0; s < 3; ++s) {
        const int D = GRID_C >> s;
        if (tid < 64) {
            int ii[3]; float ff[3];
            tri_setup(PD + tid * 3, D, ii, ff);
            TI[tid * 3 + 0] = ii[0]; TI[tid * 3 + 1] = ii[1]; TI[tid * 3 + 2] = ii[2];
            TFR[tid * 3 + 0] = ff[0]; TFR[tid * 3 + 1] = ff[1]; TFR[tid * 3 + 2] = ff[2];
        }
        __syncthreads();
        const float* gp = (s == 0) ? (const float*)g_feat_t
                        : (s == 1) ? (const float*)g_pool2t
                                   : (const float*)g_pool4t;
        {
            const int p = tid >> 2, q = tid & 3;
            if (q < 3) {
                int ix = TI[p * 3 + 0], iy = TI[p * 3 + 1], iz = TI[p * 3 + 2];
                float fx = TFR[p * 3 + 0], fy = TFR[p * 3 + 1], fz = TFR[p * 3 + 2];
                const size_t sy = (size_t)D * VD_C;
                const size_t sx = (size_t)D * sy;
                const float* b = gp + (size_t)ix * sx + (size_t)iy * sy
                               + (size_t)iz * VD_C + q * 4;
                float4 v000 = __ldg((const float4*)(b));
                float4 v001 = __ldg((const float4*)(b + VD_C));
                float4 v010 = __ldg((const float4*)(b + sy));
                float4 v011 = __ldg((const float4*)(b + sy + VD_C));
                float4 v100 = __ldg((const float4*)(b + sx));
                float4 v101 = __ldg((const float4*)(b + sx + VD_C));
                float4 v110 = __ldg((const float4*)(b + sx + sy));
                float4 v111 = __ldg((const float4*)(b + sx + sy + VD_C));
                float4 c00 = lerp4(v000, v001, fz);
                float4 c01 = lerp4(v010, v011, fz);
                float4 c10 = lerp4(v100, v101, fz);
                float4 c11 = lerp4(v110, v111, fz);
                float4 c0 = lerp4(c00, c01, fy);
                float4 c1 = lerp4(c10, c11, fy);
                float4 r  = lerp4(c0, c1, fx);
                *reinterpret_cast<float4*>(A + p * AP + s * 12 + q * 4) = r;
            }
        }
        __syncthreads();
    }

    // ---- featurenet input: sin_emb(feat,2)(180) + sin_emb(pts_d,4)(27) ----
    for (int i = tid; i < 64 * 36; i += NTHREADS) {
        int p = i & 63, d = i >> 6;
        float* row = A + p * AP;
        float f = row[d];
        float s1, c1;
        __sincosf(f, &s1, &c1);
        float s2 = 2.f * s1 * c1;
        float c2 = fmaf(-2.f * s1, s1, 1.f);
        row[36 + 2 * d]  = s1;  row[37 + 2 * d]  = s2;
        row[108 + 2 * d] = c1;  row[109 + 2 * d] = c2;
    }
    if (tid < 64) {
        const int p = tid;
        float* row = A + p * AP;
        #pragma unroll
        for (int d = 0; d < 3; ++d) {
            float v = PD[p * 3 + d];
            row[180 + d] = v;
            float s, c;
            __sincosf(v, &s, &c);
            row[183 + d * 4] = s;
            row[195 + d * 4] = c;
            #pragma unroll
            for (int k = 1; k < 4; ++k) {
                float s2 = 2.f * s * c;
                float c2 = fmaf(-2.f * s, s, 1.f);
                s = s2; c = c2;
                row[183 + d * 4 + k] = s;
                row[195 + d * 4 + k] = c;
            }
        }
        row[207] = 0.f;
    }
    __syncthreads();

    // ---- featurenet + decoder ----
    mlp_layer<128, 1>(fn_w0, fn_b0, A, AP, 207, 208, Bb, BP, WS, mb0, mb1, ph0, ph1, tid);
    __syncthreads();
    mlp_layer<128, 0>(dec_wf, dec_bf, Bb, BP, 128, 128, A, AP, WS, mb0, mb1, ph0, ph1, tid);
    __syncthreads();
    if (tid < 64) {  // append vemb; pad to 160
        float* row = A + tid * AP;
        #pragma unroll
        for (int j = 0; j < 21; ++j) row[128 + j] = VE[j];
        #pragma unroll
        for (int j = 149; j < 160; ++j) row[j] = 0.f;
    }
    __syncthreads();
    mlp_layer<64, 1>(dec_w0, dec_b0, A, AP, 149, 160, Bb, BP, WS, mb0, mb1, ph0, ph1, tid);
    __syncthreads();

    {   // final 64->3 + sigmoid (quad-parallel, weights from smem)
        const int p  = tid >> 2;
        const int l4 = tid & 3;
        float r0 = 0.f, r1 = 0.f, r2 = 0.f;
        const float* row = Bb + p * BP;
        #pragma unroll 4
        for (int k = l4; k < 64; k += 4) {
            float h = row[k];
            r0 = fmaf(h, W3B[k * 3 + 0], r0);
            r1 = fmaf(h, W3B[k * 3 + 1], r1);
            r2 = fmaf(h, W3B[k * 3 + 2], r2);
        }
        r0 += __shfl_xor_sync(0xffffffffu, r0, 1);
        r0 += __shfl_xor_sync(0xffffffffu, r0, 2);
        r1 += __shfl_xor_sync(0xffffffffu, r1, 1);
        r1 += __shfl_xor_sync(0xffffffffu, r1, 2);
        r2 += __shfl_xor_sync(0xffffffffu, r2, 1);
        r2 += __shfl_xor_sync(0xffffffffu, r2, 2);
        if (l4 == 0) {
            r0 += W3B[192]; r1 += W3B[193]; r2 += W3B[194];
            RGB[p * 3 + 0] = 1.f / (1.f + __expf(-r0));
            RGB[p * 3 + 1] = 1.f / (1.f + __expf(-r1));
            RGB[p * 3 + 2] = 1.f / (1.f + __expf(-r2));
        }
    }
    __syncthreads();

    if (tid < 3) {  // composite with white background
        float s = ALAST[0];
        for (int p = 0; p < PPR_C; ++p) s = fmaf(WGT[p], RGB[p * 3 + tid], s);
        out[(size_t)ray * 3 + tid] = s;
    }
}

// ---------------- launch ----------------
extern "C" void kernel_launch(void* const* d_in, const int* in_sizes, int n_in,
                              void* d_out, int out_size) {
    (void)in_sizes; (void)n_in; (void)out_size;
    const float* ray_pts    = (const float*)d_in[0];
    const float* viewdirs   = (const float*)d_in[1];
    const float* frame_time = (const float*)d_in[2];
    const float* feature    = (const float*)d_in[3];
    const float* density    = (const float*)d_in[4];
    const float* tn_w0 = (const float*)d_in[5];
    const float* tn_b0 = (const float*)d_in[6];
    const float* tn_w1 = (const float*)d_in[7];
    const float* tn_b1 = (const float*)d_in[8];
    const float* dt_w0 = (const float*)d_in[9];
    const float* dt_b0 = (const float*)d_in[10];
    const float* dt_w1 = (const float*)d_in[11];
    const float* dt_b1 = (const float*)d_in[12];
    const float* dt_wo = (const float*)d_in[13];
    const float* dt_bo = (const float*)d_in[14];
    const float* fn_w0 = (const float*)d_in[15];
    const float* fn_b0 = (const float*)d_in[16];
    const float* dec_wf = (const float*)d_in[17];
    const float* dec_bf = (const float*)d_in[18];
    const float* dec_w0 = (const float*)d_in[19];
    const float* dec_b0 = (const float*)d_in[20];
    const float* dec_w1 = (const float*)d_in[21];
    const float* dec_b1 = (const float*)d_in[22];
    float* out = (float*)d_out;

    cudaFuncSetAttribute(voxelmlp_main, cudaFuncAttributeMaxDynamicSharedMemorySize,
                         SMEM_BYTES);

    {
        const int V = GRID_C * GRID_C * GRID_C;
        transpose_feat<<<(V + 255) / 256, 256>>>(feature);
    }
    pool2t_kernel<<<(64 * 64 * 64 + 255) / 256, 256>>>();
    pool4t_kernel<<<(32 * 32 * 32 + 255) / 256, 256>>>();
    timenet_kernel<<<1, 128>>>(frame_time, tn_w0, tn_b0, tn_w1, tn_b1);

    voxelmlp_main<<<N_RAYS_C, NTHREADS, SMEM_BYTES>>>(
        ray_pts, viewdirs, density,
        dt_w0, dt_b0, dt_w1, dt_b1, dt_wo, dt_bo,
        fn_w0, fn_b0, dec_wf, dec_bf,
        dec_w0, dec_b0, dec_w1, dec_b1,
        out);
}

// round 16
// speedup vs baseline: 1.6825x; 1.0767x over previous
#include <cuda_runtime.h>
#include <cstdint>
#include <math.h>

// ---------------- problem constants ----------------
#define N_RAYS_C   4096
#define PPR_C      64
#define VD_C       12
#define GRID_C     128
#define ACT_SHIFT_C (-4.5951199f)   // log(1/(1-0.01) - 1)

#define AP 208
#define BP 128
#define KT 16
#define NTHREADS 256
#define NWARPS 8

// ---- smem layout (floats) ----
#define OFF_A     0
#define OFF_B     (64*AP)                    // 13312
#define OFF_WS    (OFF_B + 64*BP)            // 21504
#define OFF_W3    (OFF_WS + 2*KT*128)        // 25600 (dt_wo 384 + bias 3)
#define OFF_W3B   (OFF_W3 + 388)             // dec_w1 192 + bias 3
#define OFF_DB0   (OFF_W3B + 196)            // per-ray dec_w0 bias [64]
#define OFF_PD    (OFF_DB0 + 64)
#define OFF_ALP   (OFF_PD + 192)
#define OFF_WGT   (OFF_ALP + 64)
#define OFF_RGB   (OFF_WGT + 64)
#define OFF_VE    (OFF_RGB + 192)
#define OFF_ALAST (OFF_VE + 24)
#define OFF_TI    (OFF_ALAST + 8)
#define OFF_TFR   (OFF_TI + 192)
#define OFF_MB    (OFF_TFR + 192)            // 4 x u64: full0,full1,empty0,empty1
#define SMEM_FLOATS (OFF_MB + 8)
#define SMEM_BYTES  (SMEM_FLOATS * 4)

// ---------------- device scratch (static: no allocation) ----------------
__device__ float g_feat_t[(size_t)GRID_C * GRID_C * GRID_C * VD_C];  // [X,Y,Z,C]
__device__ float g_pool2t[(size_t)64 * 64 * 64 * VD_C];
__device__ float g_pool4t[(size_t)32 * 32 * 32 * VD_C];
__device__ float g_bias0[128];   // dt_b0 + tf @ dt_w0[27:87]

// ---------------- f32x2 / ptx helpers ----------------
__device__ __forceinline__ void ffma2(unsigned long long& d, unsigned long long a,
                                      unsigned long long b) {
    asm("fma.rn.f32x2 %0, %1, %2, %0;" : "+l"(d) : "l"(a), "l"(b));
}
__device__ __forceinline__ unsigned long long dup2(float x) {
    unsigned long long r;
    asm("mov.b64 %0, {%1, %1};" : "=l"(r) : "f"(x));
    return r;
}
__device__ __forceinline__ uint32_t smem_u32(const void* p) {
    return (uint32_t)__cvta_generic_to_shared(p);
}
__device__ __forceinline__ void mbar_init(uint32_t a, uint32_t cnt) {
    asm volatile("mbarrier.init.shared.b64 [%0], %1;" :: "r"(a), "r"(cnt) : "memory");
}
__device__ __forceinline__ void mbar_expect(uint32_t a, uint32_t bytes) {
    asm volatile("mbarrier.arrive.expect_tx.shared.b64 _, [%0], %1;"
                 :: "r"(a), "r"(bytes) : "memory");
}
__device__ __forceinline__ void mbar_arrive(uint32_t a) {
    asm volatile("mbarrier.arrive.shared.b64 _, [%0];" :: "r"(a) : "memory");
}
__device__ __forceinline__ void mbar_wait(uint32_t a, uint32_t parity) {
    asm volatile(
        "{\n\t"
        ".reg .pred P;\n"
        "LW%=:\n\t"
        "mbarrier.try_wait.parity.acquire.cta.shared::cta.b64 P, [%0], %1;\n\t"
        "@!P bra LW%=;\n\t"
        "}"
        :: "r"(a), "r"(parity) : "memory");
}
__device__ __forceinline__ void bulk_g2s(uint32_t dst, const float* src,
                                         uint32_t bytes, uint32_t mbar) {
    asm volatile(
        "cp.async.bulk.shared::cluster.global.mbarrier::complete_tx::bytes "
        "[%0], [%1], %2, [%3];"
        :: "r"(dst), "l"(src), "r"(bytes), "r"(mbar) : "memory");
}

// ---------------- grid transpose + pooling (transposed layouts) ----------------
__global__ void transpose_feat(const float* __restrict__ f) {
    int v = blockIdx.x * blockDim.x + threadIdx.x;
    const int V = GRID_C * GRID_C * GRID_C;
    if (v >= V) return;
    float vals[VD_C];
    #pragma unroll
    for (int c = 0; c < VD_C; ++c) vals[c] = __ldg(f + (size_t)c * V + v);
    float* dst = g_feat_t + (size_t)v * VD_C;
    #pragma unroll
    for (int q = 0; q < 3; ++q)
        *reinterpret_cast<float4*>(dst + q * 4) =
            make_float4(vals[q * 4], vals[q * 4 + 1], vals[q * 4 + 2], vals[q * 4 + 3]);
}

__global__ void pool2t_kernel() {
    int v = blockIdx.x * blockDim.x + threadIdx.x;
    if (v >= 64 * 64 * 64) return;
    int z = v & 63, y = (v >> 6) & 63, x = v >> 12;
    float acc[VD_C];
    #pragma unroll
    for (int c = 0; c < VD_C; ++c) acc[c] = 0.f;
    #pragma unroll
    for (int d = 0; d < 8; ++d) {
        int dx = d >> 2, dy = (d >> 1) & 1, dz = d & 1;
        const float* s = g_feat_t +
            ((((size_t)(2 * x + dx) * 128 + (2 * y + dy)) * 128 + (2 * z + dz)) * VD_C);
        #pragma unroll
        for (int q = 0; q < 3; ++q) {
            float4 b = *reinterpret_cast<const float4*>(s + q * 4);
            acc[q * 4 + 0] += b.x; acc[q * 4 + 1] += b.y;
            acc[q * 4 + 2] += b.z; acc[q * 4 + 3] += b.w;
        }
    }
    float* dst = g_pool2t + (size_t)v * VD_C;
    #pragma unroll
    for (int q = 0; q < 3; ++q)
        *reinterpret_cast<float4*>(dst + q * 4) =
            make_float4(acc[q * 4] * 0.125f, acc[q * 4 + 1] * 0.125f,
                        acc[q * 4 + 2] * 0.125f, acc[q * 4 + 3] * 0.125f);
}

__global__ void pool4t_kernel() {
    int v = blockIdx.x * blockDim.x + threadIdx.x;
    if (v >= 32 * 32 * 32) return;
    int z = v & 31, y = (v >> 5) & 31, x = v >> 10;
    float acc[VD_C];
    #pragma unroll
    for (int c = 0; c < VD_C; ++c) acc[c] = 0.f;
    #pragma unroll
    for (int d = 0; d < 8; ++d) {
        int dx = d >> 2, dy = (d >> 1) & 1, dz = d & 1;
        const float* s = g_pool2t +
            ((((size_t)(2 * x + dx) * 64 + (2 * y + dy)) * 64 + (2 * z + dz)) * VD_C);
        #pragma unroll
        for (int q = 0; q < 3; ++q) {
            float4 b = *reinterpret_cast<const float4*>(s + q * 4);
            acc[q * 4 + 0] += b.x; acc[q * 4 + 1] += b.y;
            acc[q * 4 + 2] += b.z; acc[q * 4 + 3] += b.w;
        }
    }
    float* dst = g_pool4t + (size_t)v * VD_C;
    #pragma unroll
    for (int q = 0; q < 3; ++q)
        *reinterpret_cast<float4*>(dst + q * 4) =
            make_float4(acc[q * 4] * 0.125f, acc[q * 4 + 1] * 0.125f,
                        acc[q * 4 + 2] * 0.125f, acc[q * 4 + 3] * 0.125f);
}

// ---------------- timenet + bias fold (tiny, runs once) ----------------
// g_bias0 = dt_b0 + tf @ dt_w0[27:87, :]
__global__ void timenet_kernel(const float* __restrict__ ft,
                               const float* __restrict__ w0, const float* __restrict__ b0,
                               const float* __restrict__ w1, const float* __restrict__ b1,
                               const float* __restrict__ dt_w0,
                               const float* __restrict__ dt_b0) {
    __shared__ float temb[9];
    __shared__ float h[128];
    __shared__ float tf[60];
    int tid = threadIdx.x;
    if (tid == 0) {
        float t = ft[0];
        temb[0] = t;
        #pragma unroll
        for (int k = 0; k < 4; ++k) {
            temb[1 + k] = sinf(t * (float)(1 << k));
            temb[5 + k] = cosf(t * (float)(1 << k));
        }
    }
    __syncthreads();
    {
        float v = b0[tid];
        #pragma unroll
        for (int k = 0; k < 9; ++k) v = fmaf(temb[k], w0[k * 128 + tid], v);
        h[tid] = fmaxf(v, 0.f);
    }
    __syncthreads();
    if (tid < 60) {
        float v = b1[tid];
        for (int k = 0; k < 128; ++k) v = fmaf(h[k], w1[k * 60 + tid], v);
        tf[tid] = v;
    }
    __syncthreads();
    {
        float b = dt_b0[tid];
        for (int j = 0; j < 60; ++j)
            b = fmaf(tf[j], dt_w0[(27 + j) * 128 + tid], b);
        g_bias0[tid] = b;
    }
}

// ---------------- trilerp setup ----------------
__device__ __forceinline__ void tri_setup(const float* pd, int D, int* ii, float* ff) {
    float dim = (float)(D - 1);
    float hi = dim - 1e-4f;
    #pragma unroll
    for (int c = 0; c < 3; ++c) {
        float t = (pd[c] + 1.f) * 0.5f * dim;
        t = fminf(fmaxf(t, 0.f), hi);
        float fl = floorf(t);
        ii[c] = (int)fl;
        ff[c] = t - fl;
    }
}

__device__ __forceinline__ float tri_gather1(const float* __restrict__ g, int D,
                                             int ix, int iy, int iz,
                                             float fx, float fy, float fz) {
    size_t sx = (size_t)D * D;
    int sy = D;
    const float* b = g + (size_t)ix * sx + (size_t)iy * sy + iz;
    float v000 = __ldg(b),            v001 = __ldg(b + 1);
    float v010 = __ldg(b + sy),       v011 = __ldg(b + sy + 1);
    float v100 = __ldg(b + sx),       v101 = __ldg(b + sx + 1);
    float v110 = __ldg(b + sx + sy),  v111 = __ldg(b + sx + sy + 1);
    float c00 = v000 + (v001 - v000) * fz;
    float c01 = v010 + (v011 - v010) * fz;
    float c10 = v100 + (v101 - v100) * fz;
    float c11 = v110 + (v111 - v110) * fz;
    float c0 = c00 + (c01 - c00) * fy;
    float c1 = c10 + (c11 - c10) * fy;
    return c0 + (c1 - c0) * fx;
}

__device__ __forceinline__ float4 lerp4(float4 a, float4 b, float t) {
    return make_float4(a.x + (b.x - a.x) * t, a.y + (b.y - a.y) * t,
                       a.z + (b.z - a.z) * t, a.w + (b.w - a.w) * t);
}

// ---------------- register-tiled f32x2 GEMM, full/empty mbar pipeline --------
// 64 points x OUT cols; 256 threads: ci = tid&31 (CP cols), pi = tid>>5 (8 pts)
// Consumers try_wait full[buf], compute, warp-arrive empty[buf]; tid0 waits
// empty[buf] before re-issuing TMA. No per-tile __syncthreads.
template <int OUT, int ACT>
__device__ __forceinline__ void mlp_layer(
    const float* __restrict__ W, const float* bias,
    const float* __restrict__ xs, int xp, int INA, int INP,
    float* __restrict__ ys, int yp,
    float* __restrict__ ws,
    const uint32_t* mbF, const uint32_t* mbE,
    int* phF, int* phE, int& gt, int tid) {
    constexpr int CP = OUT / 32;   // 4 (OUT=128) or 2 (OUT=64) cols per thread
    constexpr int NP = CP / 2;     // f32x2 pairs
    const int ci = tid & 31;
    const int pi = tid >> 5;       // 8 groups x 8 rows
    unsigned long long acc[8][NP];
    #pragma unroll
    for (int r = 0; r < 8; ++r)
        #pragma unroll
        for (int j = 0; j < NP; ++j) acc[r][j] = 0ull;

    const int ntiles = INP / KT;

    auto issue = [&](int t) {
        const int buf = t & 1;
        if (tid == 0) {
            if (gt >= 2) { mbar_wait(mbE[buf], (uint32_t)phE[buf]); phE[buf] ^= 1; }
            int rows = INA - t * KT; if (rows > KT) rows = KT;
            uint32_t bytes = (uint32_t)rows * OUT * 4u;
            mbar_expect(mbF[buf], bytes);
            bulk_g2s(smem_u32(ws + buf * (KT * 128)), W + (size_t)t * KT * OUT,
                     bytes, mbF[buf]);
        } else if (gt >= 2) {
            phE[buf] ^= 1;   // keep phase state consistent (unused by non-tid0)
        }
        ++gt;
    };

    issue(0);
    if (ntiles > 1) issue(1);
    for (int t = 0; t < ntiles; ++t) {
        const int buf = t & 1;
        mbar_wait(mbF[buf], (uint32_t)phF[buf]); phF[buf] ^= 1;

        const float* xb = xs + (size_t)(pi * 8) * xp + t * KT;
        const float* wb = ws + buf * (KT * 128);
        #pragma unroll
        for (int k4 = 0; k4 < KT; k4 += 4) {
            float4 xv[8];
            #pragma unroll
            for (int r = 0; r < 8; ++r)
                xv[r] = *reinterpret_cast<const float4*>(xb + r * xp + k4);
            #pragma unroll
            for (int kk = 0; kk < 4; ++kk) {
                unsigned long long xx[8];
                #pragma unroll
                for (int r = 0; r < 8; ++r) {
                    float xsv = (kk == 0) ? xv[r].x : (kk == 1) ? xv[r].y
                              : (kk == 2) ? xv[r].z : xv[r].w;
                    xx[r] = dup2(xsv);
                }
                const float* wr = wb + (k4 + kk) * OUT + ci * CP;
                if (CP == 4) {
                    ulonglong2 w2 = *reinterpret_cast<const ulonglong2*>(wr);
                    #pragma unroll
                    for (int r = 0; r < 8; ++r) {
                        ffma2(acc[r][0], xx[r], w2.x);
                        ffma2(acc[r][NP - 1], xx[r], w2.y);
                    }
                } else {
                    unsigned long long w1 = *reinterpret_cast<const unsigned long long*>(wr);
                    #pragma unroll
                    for (int r = 0; r < 8; ++r) ffma2(acc[r][0], xx[r], w1);
                }
            }
        }
        if ((tid & 31) == 0) mbar_arrive(mbE[buf]);   // this warp done with buf
        if (t + 2 < ntiles) issue(t + 2);
    }

    #pragma unroll
    for (int j = 0; j < NP; ++j) {
        float b0 = bias[ci * CP + 2 * j];
        float b1 = bias[ci * CP + 2 * j + 1];
        #pragma unroll
        for (int r = 0; r < 8; ++r) {
            float2 p = *reinterpret_cast<float2*>(&acc[r][j]);
            float v0 = p.x + b0, v1 = p.y + b1;
            if (ACT) { v0 = fmaxf(v0, 0.f); v1 = fmaxf(v1, 0.f); }
            const int row = pi * 8 + r;
            *reinterpret_cast<float2*>(ys + (size_t)row * yp + ci * CP + 2 * j) =
                make_float2(v0, v1);
        }
    }
}

// ---------------- fused main kernel: one block = one ray ----------------
__global__ void __launch_bounds__(NTHREADS, 2)
voxelmlp_main(const float* __restrict__ ray_pts,
              const float* __restrict__ viewdirs,
              const float* __restrict__ density,
              const float* __restrict__ dt_w0,
              const float* __restrict__ dt_w1, const float* __restrict__ dt_b1,
              const float* __restrict__ dt_wo, const float* __restrict__ dt_bo,
              const float* __restrict__ fn_w0, const float* __restrict__ fn_b0,
              const float* __restrict__ dec_wf, const float* __restrict__ dec_bf,
              const float* __restrict__ dec_w0, const float* __restrict__ dec_b0,
              const float* __restrict__ dec_w1, const float* __restrict__ dec_b1,
              float* __restrict__ out) {
    extern __shared__ float sm[];
    float* A     = sm + OFF_A;     // [64][208]
    float* Bb    = sm + OFF_B;     // [64][128]
    float* WS    = sm + OFF_WS;    // [2][16][128]
    float* W3    = sm + OFF_W3;
    float* W3B   = sm + OFF_W3B;
    float* DB0   = sm + OFF_DB0;   // per-ray dec_w0 bias [64]
    float* PD    = sm + OFF_PD;
    float* ALP   = sm + OFF_ALP;
    float* WGT   = sm + OFF_WGT;
    float* RGB   = sm + OFF_RGB;
    float* VE    = sm + OFF_VE;
    float* ALAST = sm + OFF_ALAST;
    int*   TI    = reinterpret_cast<int*>(sm + OFF_TI);
    float* TFR   = sm + OFF_TFR;
    uint32_t mbF[2], mbE[2];
    mbF[0] = smem_u32(sm + OFF_MB);
    mbF[1] = mbF[0] + 8;
    mbE[0] = mbF[0] + 16;
    mbE[1] = mbF[0] + 24;

    const int tid   = threadIdx.x;
    const int ray   = blockIdx.x;
    const int gbase = ray * PPR_C;
    int phF[2] = {0, 0}, phE[2] = {0, 0};
    int gt = 0;

    // ---- init: zero weight buffers (NaN-garbage guard), init mbarriers ----
    for (int i = tid; i < 2 * KT * 128; i += NTHREADS) WS[i] = 0.f;
    if (tid == 0) {
        mbar_init(mbF[0], 1); mbar_init(mbF[1], 1);
        mbar_init(mbE[0], NWARPS); mbar_init(mbE[1], NWARPS);
    }
    asm volatile("fence.proxy.async.shared::cta;" ::: "memory");

    // stage small weights to smem
    for (int i = tid; i < 128 * 3; i += NTHREADS) W3[i] = __ldg(dt_wo + i);
    if (tid < 3) W3[384 + tid] = __ldg(dt_bo + tid);
    for (int i = tid; i < 64 * 3; i += NTHREADS) W3B[i] = __ldg(dec_w1 + i);
    if (tid < 3) W3B[192 + tid] = __ldg(dec_b1 + tid);

    // ---- phase 0: deform input X = pts_emb(27), pad -> 32 (tf folded in bias)
    if (tid < 64) {
        const int p = tid;
        float* row = A + p * AP;
        #pragma unroll
        for (int d = 0; d < 3; ++d) {
            float v = ray_pts[(size_t)(gbase + p) * 3 + d];
            row[d] = v;
            float s, c;
            __sincosf(v, &s, &c);
            row[3 + d * 4]  = s;
            row[15 + d * 4] = c;
            #pragma unroll
            for (int k = 1; k < 4; ++k) {
                float s2 = 2.f * s * c;
                float c2 = fmaf(-2.f * s, s, 1.f);
                s = s2; c = c2;
                row[3 + d * 4 + k]  = s;
                row[15 + d * 4 + k] = c;
            }
        }
        #pragma unroll
        for (int j = 27; j < 32; ++j) row[j] = 0.f;
    }
    if (tid >= 64 && tid < 67) {  // view embedding
        const int d = tid - 64;
        float v = viewdirs[(size_t)ray * 3 + d];
        VE[d] = v;
        float s, c;
        __sincosf(v, &s, &c);
        VE[3 + d * 3]  = s;
        VE[12 + d * 3] = c;
        #pragma unroll
        for (int k = 1; k < 3; ++k) {
            float s2 = 2.f * s * c;
            float c2 = fmaf(-2.f * s, s, 1.f);
            s = s2; c = c2;
            VE[3 + d * 3 + k]  = s;
            VE[12 + d * 3 + k] = c;
        }
    }
    __syncthreads();

    // per-ray fold: DB0 = dec_b0 + vemb @ dec_w0[128:149, :]
    if (tid < 64) {
        float b = __ldg(dec_b0 + tid);
        #pragma unroll
        for (int j = 0; j < 21; ++j)
            b = fmaf(VE[j], __ldg(dec_w0 + (128 + j) * 64 + tid), b);
        DB0[tid] = b;
    }

    // ---- deformation net (layer0 K=27 pad 32; bias = g_bias0) ----
    mlp_layer<128, 1>(dt_w0, g_bias0, A, AP, 27, 32, Bb, BP, WS,
                      mbF, mbE, phF, phE, gt, tid);
    __syncthreads();
    mlp_layer<128, 1>(dt_w1, dt_b1, Bb, BP, 128, 128, A, AP, WS,
                      mbF, mbE, phF, phE, gt, tid);
    __syncthreads();

    {   // dx = H @ dt_wo + dt_bo (quad-parallel, weights from smem)
        const int p  = tid >> 2;
        const int l4 = tid & 3;
        float d0 = 0.f, d1 = 0.f, d2 = 0.f;
        const float* row = A + p * AP;
        #pragma unroll 8
        for (int k = l4; k < 128; k += 4) {
            float h = row[k];
            d0 = fmaf(h, W3[k * 3 + 0], d0);
            d1 = fmaf(h, W3[k * 3 + 1], d1);
            d2 = fmaf(h, W3[k * 3 + 2], d2);
        }
        d0 += __shfl_xor_sync(0xffffffffu, d0, 1);
        d0 += __shfl_xor_sync(0xffffffffu, d0, 2);
        d1 += __shfl_xor_sync(0xffffffffu, d1, 1);
        d1 += __shfl_xor_sync(0xffffffffu, d1, 2);
        d2 += __shfl_xor_sync(0xffffffffu, d2, 1);
        d2 += __shfl_xor_sync(0xffffffffu, d2, 2);
        if (l4 == 0) {
            PD[p * 3 + 0] = ray_pts[(size_t)(gbase + p) * 3 + 0] + d0 + W3[384];
            PD[p * 3 + 1] = ray_pts[(size_t)(gbase + p) * 3 + 1] + d1 + W3[385];
            PD[p * 3 + 2] = ray_pts[(size_t)(gbase + p) * 3 + 2] + d2 + W3[386];
        }
    }
    __syncthreads();

    // ---- density -> alpha ----
    if (tid < 64) {
        const int p = tid;
        int ii[3]; float ff[3];
        tri_setup(PD + p * 3, GRID_C, ii, ff);
        float dens = tri_gather1(density, GRID_C, ii[0], ii[1], ii[2],
                                 ff[0], ff[1], ff[2]);
        float x = dens + ACT_SHIFT_C;
        float sp = (x > 20.f) ? x : log1pf(__expf(x));
        ALP[p] = 1.f - __expf(-sp * 0.5f);
    }
    __syncthreads();
    if (tid == 0) {  // per-ray exclusive cumprod
        float T = 1.f;
        for (int i = 0; i < PPR_C; ++i) {
            float a = ALP[i];
            WGT[i] = a * T;
            T *= (1.f - a);
        }
        ALAST[0] = T;
    }

    // ---- 3-scale feature trilerp (transposed grids, float4 gathers) ----
    #pragma unroll 1
    for (int s = 0; s < 3; ++s) {
        const int D = GRID_C >> s;
        if (tid < 64) {
            int ii[3]; float ff[3];
            tri_setup(PD + tid * 3, D, ii, ff);
            TI[tid * 3 + 0] = ii[0]; TI[tid * 3 + 1] = ii[1]; TI[tid * 3 + 2] = ii[2];
            TFR[tid * 3 + 0] = ff[0]; TFR[tid * 3 + 1] = ff[1]; TFR[tid * 3 + 2] = ff[2];
        }
        __syncthreads();
        const float* gp = (s == 0) ? (const float*)g_feat_t
                        : (s == 1) ? (const float*)g_pool2t
                                   : (const float*)g_pool4t;
        {
            const int p = tid >> 2, q = tid & 3;
            if (q < 3) {
                int ix = TI[p * 3 + 0], iy = TI[p * 3 + 1], iz = TI[p * 3 + 2];
                float fx = TFR[p * 3 + 0], fy = TFR[p * 3 + 1], fz = TFR[p * 3 + 2];
                const size_t sy = (size_t)D * VD_C;
                const size_t sx = (size_t)D * sy;
                const float* b = gp + (size_t)ix * sx + (size_t)iy * sy
                               + (size_t)iz * VD_C + q * 4;
                float4 v000 = __ldg((const float4*)(b));
                float4 v001 = __ldg((const float4*)(b + VD_C));
                float4 v010 = __ldg((const float4*)(b + sy));
                float4 v011 = __ldg((const float4*)(b + sy + VD_C));
                float4 v100 = __ldg((const float4*)(b + sx));
                float4 v101 = __ldg((const float4*)(b + sx + VD_C));
                float4 v110 = __ldg((const float4*)(b + sx + sy));
                float4 v111 = __ldg((const float4*)(b + sx + sy + VD_C));
                float4 c00 = lerp4(v000, v001, fz);
                float4 c01 = lerp4(v010, v011, fz);
                float4 c10 = lerp4(v100, v101, fz);
                float4 c11 = lerp4(v110, v111, fz);
                float4 c0 = lerp4(c00, c01, fy);
                float4 c1 = lerp4(c10, c11, fy);
                float4 r  = lerp4(c0, c1, fx);
                *reinterpret_cast<float4*>(A + p * AP + s * 12 + q * 4) = r;
            }
        }
        __syncthreads();
    }

    // ---- featurenet input: sin_emb(feat,2)(180) + sin_emb(pts_d,4)(27) ----
    for (int i = tid; i < 64 * 36; i += NTHREADS) {
        int p = i & 63, d = i >> 6;
        float* row = A + p * AP;
        float f = row[d];
        float s1, c1;
        __sincosf(f, &s1, &c1);
        float s2 = 2.f * s1 * c1;
        float c2 = fmaf(-2.f * s1, s1, 1.f);
        row[36 + 2 * d]  = s1;  row[37 + 2 * d]  = s2;
        row[108 + 2 * d] = c1;  row[109 + 2 * d] = c2;
    }
    if (tid < 64) {
        const int p = tid;
        float* row = A + p * AP;
        #pragma unroll
        for (int d = 0; d < 3; ++d) {
            float v = PD[p * 3 + d];
            row[180 + d] = v;
            float s, c;
            __sincosf(v, &s, &c);
            row[183 + d * 4] = s;
            row[195 + d * 4] = c;
            #pragma unroll
            for (int k = 1; k < 4; ++k) {
                float s2 = 2.f * s * c;
                float c2 = fmaf(-2.f * s, s, 1.f);
                s = s2; c = c2;
                row[183 + d * 4 + k] = s;
                row[195 + d * 4 + k] = c;
            }
        }
        row[207] = 0.f;
    }
    __syncthreads();

    // ---- featurenet + decoder ----
    mlp_layer<128, 1>(fn_w0, fn_b0, A, AP, 207, 208, Bb, BP, WS,
                      mbF, mbE, phF, phE, gt, tid);
    __syncthreads();
    mlp_layer<128, 0>(dec_wf, dec_bf, Bb, BP, 128, 128, A, AP, WS,
                      mbF, mbE, phF, phE, gt, tid);
    __syncthreads();
    // vemb folded into DB0 -> dec_w0 consumes only fl (K=128)
    mlp_layer<64, 1>(dec_w0, DB0, A, AP, 128, 128, Bb, BP, WS,
                     mbF, mbE, phF, phE, gt, tid);
    __syncthreads();

    {   // final 64->3 + sigmoid (quad-parallel, weights from smem)
        const int p  = tid >> 2;
        const int l4 = tid & 3;
        float r0 = 0.f, r1 = 0.f, r2 = 0.f;
        const float* row = Bb + p * BP;
        #pragma unroll 4
        for (int k = l4; k < 64; k += 4) {
            float h = row[k];
            r0 = fmaf(h, W3B[k * 3 + 0], r0);
            r1 = fmaf(h, W3B[k * 3 + 1], r1);
            r2 = fmaf(h, W3B[k * 3 + 2], r2);
        }
        r0 += __shfl_xor_sync(0xffffffffu, r0, 1);
        r0 += __shfl_xor_sync(0xffffffffu, r0, 2);
        r1 += __shfl_xor_sync(0xffffffffu, r1, 1);
        r1 += __shfl_xor_sync(0xffffffffu, r1, 2);
        r2 += __shfl_xor_sync(0xffffffffu, r2, 1);
        r2 += __shfl_xor_sync(0xffffffffu, r2, 2);
        if (l4 == 0) {
            r0 += W3B[192]; r1 += W3B[193]; r2 += W3B[194];
            RGB[p * 3 + 0] = 1.f / (1.f + __expf(-r0));
            RGB[p * 3 + 1] = 1.f / (1.f + __expf(-r1));
            RGB[p * 3 + 2] = 1.f / (1.f + __expf(-r2));
        }
    }
    __syncthreads();

    if (tid < 3) {  // composite with white background
        float s = ALAST[0];
        for (int p = 0; p < PPR_C; ++p) s = fmaf(WGT[p], RGB[p * 3 + tid], s);
        out[(size_t)ray * 3 + tid] = s;
    }
}

// ---------------- launch ----------------
extern "C" void kernel_launch(void* const* d_in, const int* in_sizes, int n_in,
                              void* d_out, int out_size) {
    (void)in_sizes; (void)n_in; (void)out_size;
    const float* ray_pts    = (const float*)d_in[0];
    const float* viewdirs   = (const float*)d_in[1];
    const float* frame_time = (const float*)d_in[2];
    const float* feature    = (const float*)d_in[3];
    const float* density    = (const float*)d_in[4];
    const float* tn_w0 = (const float*)d_in[5];
    const float* tn_b0 = (const float*)d_in[6];
    const float* tn_w1 = (const float*)d_in[7];
    const float* tn_b1 = (const float*)d_in[8];
    const float* dt_w0 = (const float*)d_in[9];
    const float* dt_b0 = (const float*)d_in[10];
    const float* dt_w1 = (const float*)d_in[11];
    const float* dt_b1 = (const float*)d_in[12];
    const float* dt_wo = (const float*)d_in[13];
    const float* dt_bo = (const float*)d_in[14];
    const float* fn_w0 = (const float*)d_in[15];
    const float* fn_b0 = (const float*)d_in[16];
    const float* dec_wf = (const float*)d_in[17];
    const float* dec_bf = (const float*)d_in[18];
    const float* dec_w0 = (const float*)d_in[19];
    const float* dec_b0 = (const float*)d_in[20];
    const float* dec_w1 = (const float*)d_in[21];
    const float* dec_b1 = (const float*)d_in[22];
    float* out = (float*)d_out;

    cudaFuncSetAttribute(voxelmlp_main, cudaFuncAttributeMaxDynamicSharedMemorySize,
                         SMEM_BYTES);

    {
        const int V = GRID_C * GRID_C * GRID_C;
        transpose_feat<<<(V + 255) / 256, 256>>>(feature);
    }
    pool2t_kernel<<<(64 * 64 * 64 + 255) / 256, 256>>>();
    pool4t_kernel<<<(32 * 32 * 32 + 255) / 256, 256>>>();
    timenet_kernel<<<1, 128>>>(frame_time, tn_w0, tn_b0, tn_w1, tn_b1,
                               dt_w0, dt_b0);

    voxelmlp_main<<<N_RAYS_C, NTHREADS, SMEM_BYTES>>>(
        ray_pts, viewdirs, density,
        dt_w0, dt_w1, dt_b1, dt_wo, dt_bo,
        fn_w0, fn_b0, dec_wf, dec_bf,
        dec_w0, dec_b0, dec_w1, dec_b1,
        out);
}

// round 17
// speedup vs baseline: 1.9999x; 1.1887x over previous
#include <cuda_runtime.h>
#include <cstdint>
#include <math.h>

// ---------------- problem constants ----------------
#define N_RAYS_C   4096
#define PPR_C      64
#define VD_C       12
#define GRID_C     128
#define ACT_SHIFT_C (-4.5951199f)   // log(1/(1-0.01) - 1)

#define AP 208
#define BP 128
#define KT 16
#define NTHREADS 256
#define NWARPS 8

// ---- smem layout (floats) ----
#define OFF_A     0
#define OFF_B     (64*AP)                    // 13312
#define OFF_WS    (OFF_B + 64*BP)            // 21504
#define OFF_W3    (OFF_WS + 2*KT*128)        // 25600 (dt_wo 384 + bias 3)
#define OFF_W3B   (OFF_W3 + 388)             // dec_w1 192 + bias 3
#define OFF_DB0   (OFF_W3B + 196)            // per-ray dec' bias [64]
#define OFF_PD    (OFF_DB0 + 64)
#define OFF_ALP   (OFF_PD + 192)
#define OFF_WGT   (OFF_ALP + 64)
#define OFF_RGB   (OFF_WGT + 64)
#define OFF_VE    (OFF_RGB + 192)
#define OFF_ALAST (OFF_VE + 24)
#define OFF_MB    (OFF_ALAST + 8)            // 4 x u64: full0,full1,empty0,empty1
#define SMEM_FLOATS (OFF_MB + 8)
#define SMEM_BYTES  (SMEM_FLOATS * 4)

// ---------------- device scratch (static: no allocation) ----------------
__device__ float g_feat_t[(size_t)GRID_C * GRID_C * GRID_C * VD_C];  // [X,Y,Z,C]
__device__ float g_pool2t[(size_t)64 * 64 * 64 * VD_C];
__device__ float g_pool4t[(size_t)32 * 32 * 32 * VD_C];
__device__ float g_bias0[128];   // dt_b0 + tf @ dt_w0[27:87]
__device__ float g_decw[128 * 64];  // dec_wf @ dec_w0[:128]
__device__ float g_decb[64];        // dec_b0 + dec_bf @ dec_w0[:128]

// ---------------- f32x2 / ptx helpers ----------------
__device__ __forceinline__ void ffma2(unsigned long long& d, unsigned long long a,
                                      unsigned long long b) {
    asm("fma.rn.f32x2 %0, %1, %2, %0;" : "+l"(d) : "l"(a), "l"(b));
}
__device__ __forceinline__ unsigned long long dup2(float x) {
    unsigned long long r;
    asm("mov.b64 %0, {%1, %1};" : "=l"(r) : "f"(x));
    return r;
}
__device__ __forceinline__ uint32_t smem_u32(const void* p) {
    return (uint32_t)__cvta_generic_to_shared(p);
}
__device__ __forceinline__ void mbar_init(uint32_t a, uint32_t cnt) {
    asm volatile("mbarrier.init.shared.b64 [%0], %1;" :: "r"(a), "r"(cnt) : "memory");
}
__device__ __forceinline__ void mbar_expect(uint32_t a, uint32_t bytes) {
    asm volatile("mbarrier.arrive.expect_tx.shared.b64 _, [%0], %1;"
                 :: "r"(a), "r"(bytes) : "memory");
}
__device__ __forceinline__ void mbar_arrive(uint32_t a) {
    asm volatile("mbarrier.arrive.shared.b64 _, [%0];" :: "r"(a) : "memory");
}
__device__ __forceinline__ void mbar_wait(uint32_t a, uint32_t parity) {
    asm volatile(
        "{\n\t"
        ".reg .pred P;\n"
        "LW%=:\n\t"
        "mbarrier.try_wait.parity.acquire.cta.shared::cta.b64 P, [%0], %1;\n\t"
        "@!P bra LW%=;\n\t"
        "}"
        :: "r"(a), "r"(parity) : "memory");
}
__device__ __forceinline__ void bulk_g2s(uint32_t dst, const float* src,
                                         uint32_t bytes, uint32_t mbar) {
    asm volatile(
        "cp.async.bulk.shared::cluster.global.mbarrier::complete_tx::bytes "
        "[%0], [%1], %2, [%3];"
        :: "r"(dst), "l"(src), "r"(bytes), "r"(mbar) : "memory");
}

// ---------------- grid transpose + pooling (transposed layouts) ----------------
__global__ void transpose_feat(const float* __restrict__ f) {
    int v = blockIdx.x * blockDim.x + threadIdx.x;
    const int V = GRID_C * GRID_C * GRID_C;
    if (v >= V) return;
    float vals[VD_C];
    #pragma unroll
    for (int c = 0; c < VD_C; ++c) vals[c] = __ldg(f + (size_t)c * V + v);
    float* dst = g_feat_t + (size_t)v * VD_C;
    #pragma unroll
    for (int q = 0; q < 3; ++q)
        *reinterpret_cast<float4*>(dst + q * 4) =
            make_float4(vals[q * 4], vals[q * 4 + 1], vals[q * 4 + 2], vals[q * 4 + 3]);
}

__global__ void pool2t_kernel() {
    int v = blockIdx.x * blockDim.x + threadIdx.x;
    if (v >= 64 * 64 * 64) return;
    int z = v & 63, y = (v >> 6) & 63, x = v >> 12;
    float acc[VD_C];
    #pragma unroll
    for (int c = 0; c < VD_C; ++c) acc[c] = 0.f;
    #pragma unroll
    for (int d = 0; d < 8; ++d) {
        int dx = d >> 2, dy = (d >> 1) & 1, dz = d & 1;
        const float* s = g_feat_t +
            ((((size_t)(2 * x + dx) * 128 + (2 * y + dy)) * 128 + (2 * z + dz)) * VD_C);
        #pragma unroll
        for (int q = 0; q < 3; ++q) {
            float4 b = *reinterpret_cast<const float4*>(s + q * 4);
            acc[q * 4 + 0] += b.x; acc[q * 4 + 1] += b.y;
            acc[q * 4 + 2] += b.z; acc[q * 4 + 3] += b.w;
        }
    }
    float* dst = g_pool2t + (size_t)v * VD_C;
    #pragma unroll
    for (int q = 0; q < 3; ++q)
        *reinterpret_cast<float4*>(dst + q * 4) =
            make_float4(acc[q * 4] * 0.125f, acc[q * 4 + 1] * 0.125f,
                        acc[q * 4 + 2] * 0.125f, acc[q * 4 + 3] * 0.125f);
}

__global__ void pool4t_kernel() {
    int v = blockIdx.x * blockDim.x + threadIdx.x;
    if (v >= 32 * 32 * 32) return;
    int z = v & 31, y = (v >> 5) & 31, x = v >> 10;
    float acc[VD_C];
    #pragma unroll
    for (int c = 0; c < VD_C; ++c) acc[c] = 0.f;
    #pragma unroll
    for (int d = 0; d < 8; ++d) {
        int dx = d >> 2, dy = (d >> 1) & 1, dz = d & 1;
        const float* s = g_pool2t +
            ((((size_t)(2 * x + dx) * 64 + (2 * y + dy)) * 64 + (2 * z + dz)) * VD_C);
        #pragma unroll
        for (int q = 0; q < 3; ++q) {
            float4 b = *reinterpret_cast<const float4*>(s + q * 4);
            acc[q * 4 + 0] += b.x; acc[q * 4 + 1] += b.y;
            acc[q * 4 + 2] += b.z; acc[q * 4 + 3] += b.w;
        }
    }
    float* dst = g_pool4t + (size_t)v * VD_C;
    #pragma unroll
    for (int q = 0; q < 3; ++q)
        *reinterpret_cast<float4*>(dst + q * 4) =
            make_float4(acc[q * 4] * 0.125f, acc[q * 4 + 1] * 0.125f,
                        acc[q * 4 + 2] * 0.125f, acc[q * 4 + 3] * 0.125f);
}

// ---------------- timenet + bias fold (tiny, runs once) ----------------
__global__ void timenet_kernel(const float* __restrict__ ft,
                               const float* __restrict__ w0, const float* __restrict__ b0,
                               const float* __restrict__ w1, const float* __restrict__ b1,
                               const float* __restrict__ dt_w0,
                               const float* __restrict__ dt_b0) {
    __shared__ float temb[9];
    __shared__ float h[128];
    __shared__ float tf[60];
    int tid = threadIdx.x;
    if (tid == 0) {
        float t = ft[0];
        temb[0] = t;
        #pragma unroll
        for (int k = 0; k < 4; ++k) {
            temb[1 + k] = sinf(t * (float)(1 << k));
            temb[5 + k] = cosf(t * (float)(1 << k));
        }
    }
    __syncthreads();
    {
        float v = b0[tid];
        #pragma unroll
        for (int k = 0; k < 9; ++k) v = fmaf(temb[k], w0[k * 128 + tid], v);
        h[tid] = fmaxf(v, 0.f);
    }
    __syncthreads();
    if (tid < 60) {
        float v = b1[tid];
        for (int k = 0; k < 128; ++k) v = fmaf(h[k], w1[k * 60 + tid], v);
        tf[tid] = v;
    }
    __syncthreads();
    {
        float b = dt_b0[tid];
        for (int j = 0; j < 60; ++j)
            b = fmaf(tf[j], dt_w0[(27 + j) * 128 + tid], b);
        g_bias0[tid] = b;
    }
}

// ---------------- decoder fold: g_decw = dec_wf @ dec_w0[:128]  --------------
// blocks 0..127 compute row i; block 128 computes the bias fold.
__global__ void fold_dec(const float* __restrict__ dec_wf,
                         const float* __restrict__ dec_bf,
                         const float* __restrict__ dec_w0,
                         const float* __restrict__ dec_b0) {
    const int j = threadIdx.x;   // 0..63
    const int i = blockIdx.x;    // 0..128
    if (i < 128) {
        float s = 0.f;
        for (int k = 0; k < 128; ++k)
            s = fmaf(__ldg(dec_wf + i * 128 + k), __ldg(dec_w0 + k * 64 + j), s);
        g_decw[i * 64 + j] = s;
    } else {
        float s = __ldg(dec_b0 + j);
        for (int k = 0; k < 128; ++k)
            s = fmaf(__ldg(dec_bf + k), __ldg(dec_w0 + k * 64 + j), s);
        g_decb[j] = s;
    }
}

// ---------------- trilerp helpers ----------------
__device__ __forceinline__ float tri_gather1(const float* __restrict__ g, int D,
                                             int ix, int iy, int iz,
                                             float fx, float fy, float fz) {
    size_t sx = (size_t)D * D;
    int sy = D;
    const float* b = g + (size_t)ix * sx + (size_t)iy * sy + iz;
    float v000 = __ldg(b),            v001 = __ldg(b + 1);
    float v010 = __ldg(b + sy),       v011 = __ldg(b + sy + 1);
    float v100 = __ldg(b + sx),       v101 = __ldg(b + sx + 1);
    float v110 = __ldg(b + sx + sy),  v111 = __ldg(b + sx + sy + 1);
    float c00 = v000 + (v001 - v000) * fz;
    float c01 = v010 + (v011 - v010) * fz;
    float c10 = v100 + (v101 - v100) * fz;
    float c11 = v110 + (v111 - v110) * fz;
    float c0 = c00 + (c01 - c00) * fy;
    float c1 = c10 + (c11 - c10) * fy;
    return c0 + (c1 - c0) * fx;
}

__device__ __forceinline__ float4 lerp4(float4 a, float4 b, float t) {
    return make_float4(a.x + (b.x - a.x) * t, a.y + (b.y - a.y) * t,
                       a.z + (b.z - a.z) * t, a.w + (b.w - a.w) * t);
}

// ---------------- register-tiled f32x2 GEMM, full/empty mbar pipeline --------
template <int OUT, int ACT>
__device__ __forceinline__ void mlp_layer(
    const float* __restrict__ W, const float* bias,
    const float* __restrict__ xs, int xp, int INA, int INP,
    float* __restrict__ ys, int yp,
    float* __restrict__ ws,
    const uint32_t* mbF, const uint32_t* mbE,
    int* phF, int* phE, int& gt, int tid) {
    constexpr int CP = OUT / 32;   // 4 (OUT=128) or 2 (OUT=64) cols per thread
    constexpr int NP = CP / 2;     // f32x2 pairs
    const int ci = tid & 31;
    const int pi = tid >> 5;       // 8 groups x 8 rows
    unsigned long long acc[8][NP];
    #pragma unroll
    for (int r = 0; r < 8; ++r)
        #pragma unroll
        for (int j = 0; j < NP; ++j) acc[r][j] = 0ull;

    const int ntiles = INP / KT;

    auto issue = [&](int t) {
        const int buf = t & 1;
        if (tid == 0) {
            if (gt >= 2) { mbar_wait(mbE[buf], (uint32_t)phE[buf]); phE[buf] ^= 1; }
            int rows = INA - t * KT; if (rows > KT) rows = KT;
            uint32_t bytes = (uint32_t)rows * OUT * 4u;
            mbar_expect(mbF[buf], bytes);
            bulk_g2s(smem_u32(ws + buf * (KT * 128)), W + (size_t)t * KT * OUT,
                     bytes, mbF[buf]);
        } else if (gt >= 2) {
            phE[buf] ^= 1;
        }
        ++gt;
    };

    issue(0);
    if (ntiles > 1) issue(1);
    for (int t = 0; t < ntiles; ++t) {
        const int buf = t & 1;
        mbar_wait(mbF[buf], (uint32_t)phF[buf]); phF[buf] ^= 1;

        const float* xb = xs + (size_t)(pi * 8) * xp + t * KT;
        const float* wb = ws + buf * (KT * 128);
        #pragma unroll
        for (int k4 = 0; k4 < KT; k4 += 4) {
            float4 xv[8];
            #pragma unroll
            for (int r = 0; r < 8; ++r)
                xv[r] = *reinterpret_cast<const float4*>(xb + r * xp + k4);
            #pragma unroll
            for (int kk = 0; kk < 4; ++kk) {
                unsigned long long xx[8];
                #pragma unroll
                for (int r = 0; r < 8; ++r) {
                    float xsv = (kk == 0) ? xv[r].x : (kk == 1) ? xv[r].y
                              : (kk == 2) ? xv[r].z : xv[r].w;
                    xx[r] = dup2(xsv);
                }
                const float* wr = wb + (k4 + kk) * OUT + ci * CP;
                if (CP == 4) {
                    ulonglong2 w2 = *reinterpret_cast<const ulonglong2*>(wr);
                    #pragma unroll
                    for (int r = 0; r < 8; ++r) {
                        ffma2(acc[r][0], xx[r], w2.x);
                        ffma2(acc[r][NP - 1], xx[r], w2.y);
                    }
                } else {
                    unsigned long long w1 = *reinterpret_cast<const unsigned long long*>(wr);
                    #pragma unroll
                    for (int r = 0; r < 8; ++r) ffma2(acc[r][0], xx[r], w1);
                }
            }
        }
        if ((tid & 31) == 0) mbar_arrive(mbE[buf]);
        if (t + 2 < ntiles) issue(t + 2);
    }

    #pragma unroll
    for (int j = 0; j < NP; ++j) {
        float b0 = bias[ci * CP + 2 * j];
        float b1 = bias[ci * CP + 2 * j + 1];
        #pragma unroll
        for (int r = 0; r < 8; ++r) {
            float2 p = *reinterpret_cast<float2*>(&acc[r][j]);
            float v0 = p.x + b0, v1 = p.y + b1;
            if (ACT) { v0 = fmaxf(v0, 0.f); v1 = fmaxf(v1, 0.f); }
            const int row = pi * 8 + r;
            *reinterpret_cast<float2*>(ys + (size_t)row * yp + ci * CP + 2 * j) =
                make_float2(v0, v1);
        }
    }
}

// ---------------- fused main kernel: one block = one ray ----------------
__global__ void __launch_bounds__(NTHREADS, 2)
voxelmlp_main(const float* __restrict__ ray_pts,
              const float* __restrict__ viewdirs,
              const float* __restrict__ density,
              const float* __restrict__ dt_w0,
              const float* __restrict__ dt_w1, const float* __restrict__ dt_b1,
              const float* __restrict__ dt_wo, const float* __restrict__ dt_bo,
              const float* __restrict__ fn_w0, const float* __restrict__ fn_b0,
              const float* __restrict__ dec_w0,
              const float* __restrict__ dec_w1, const float* __restrict__ dec_b1,
              float* __restrict__ out) {
    extern __shared__ float sm[];
    float* A     = sm + OFF_A;     // [64][208]
    float* Bb    = sm + OFF_B;     // [64][128]
    float* WS    = sm + OFF_WS;    // [2][16][128]
    float* W3    = sm + OFF_W3;
    float* W3B   = sm + OFF_W3B;
    float* DB0   = sm + OFF_DB0;   // per-ray dec' bias [64]
    float* PD    = sm + OFF_PD;
    float* ALP   = sm + OFF_ALP;
    float* WGT   = sm + OFF_WGT;
    float* RGB   = sm + OFF_RGB;
    float* VE    = sm + OFF_VE;
    float* ALAST = sm + OFF_ALAST;
    uint32_t mbF[2], mbE[2];
    mbF[0] = smem_u32(sm + OFF_MB);
    mbF[1] = mbF[0] + 8;
    mbE[0] = mbF[0] + 16;
    mbE[1] = mbF[0] + 24;

    const int tid   = threadIdx.x;
    const int ray   = blockIdx.x;
    const int gbase = ray * PPR_C;
    int phF[2] = {0, 0}, phE[2] = {0, 0};
    int gt = 0;

    // ---- init: zero weight buffers (NaN-garbage guard), init mbarriers ----
    for (int i = tid; i < 2 * KT * 128; i += NTHREADS) WS[i] = 0.f;
    if (tid == 0) {
        mbar_init(mbF[0], 1); mbar_init(mbF[1], 1);
        mbar_init(mbE[0], NWARPS); mbar_init(mbE[1], NWARPS);
    }
    asm volatile("fence.proxy.async.shared::cta;" ::: "memory");

    // stage small weights to smem
    for (int i = tid; i < 128 * 3; i += NTHREADS) W3[i] = __ldg(dt_wo + i);
    if (tid < 3) W3[384 + tid] = __ldg(dt_bo + tid);
    for (int i = tid; i < 64 * 3; i += NTHREADS) W3B[i] = __ldg(dec_w1 + i);
    if (tid < 3) W3B[192 + tid] = __ldg(dec_b1 + tid);

    // ---- phase 0: deform input X = pts_emb(27) over 192 threads ----
    if (tid < 192) {
        const int p = tid & 63;
        const int d = tid >> 6;   // 0..2
        float* row = A + p * AP;
        float v = ray_pts[(size_t)(gbase + p) * 3 + d];
        row[d] = v;
        float s, c;
        __sincosf(v, &s, &c);
        row[3 + d * 4]  = s;
        row[15 + d * 4] = c;
        #pragma unroll
        for (int k = 1; k < 4; ++k) {
            float s2 = 2.f * s * c;
            float c2 = fmaf(-2.f * s, s, 1.f);
            s = s2; c = c2;
            row[3 + d * 4 + k]  = s;
            row[15 + d * 4 + k] = c;
        }
        if (d == 0) {
            #pragma unroll
            for (int j = 27; j < 32; ++j) row[j] = 0.f;
        }
    }
    if (tid >= 192 && tid < 195) {  // view embedding
        const int d = tid - 192;
        float v = viewdirs[(size_t)ray * 3 + d];
        VE[d] = v;
        float s, c;
        __sincosf(v, &s, &c);
        VE[3 + d * 3]  = s;
        VE[12 + d * 3] = c;
        #pragma unroll
        for (int k = 1; k < 3; ++k) {
            float s2 = 2.f * s * c;
            float c2 = fmaf(-2.f * s, s, 1.f);
            s = s2; c = c2;
            VE[3 + d * 3 + k]  = s;
            VE[12 + d * 3 + k] = c;
        }
    }
    __syncthreads();

    // per-ray fold: DB0 = g_decb + vemb @ dec_w0[128:149, :]
    if (tid < 64) {
        float b = g_decb[tid];
        #pragma unroll
        for (int j = 0; j < 21; ++j)
            b = fmaf(VE[j], __ldg(dec_w0 + (128 + j) * 64 + tid), b);
        DB0[tid] = b;
    }

    // ---- deformation net (layer0 K=27 pad 32; bias = g_bias0) ----
    mlp_layer<128, 1>(dt_w0, g_bias0, A, AP, 27, 32, Bb, BP, WS,
                      mbF, mbE, phF, phE, gt, tid);
    __syncthreads();
    mlp_layer<128, 1>(dt_w1, dt_b1, Bb, BP, 128, 128, A, AP, WS,
                      mbF, mbE, phF, phE, gt, tid);
    __syncthreads();

    {   // dx = H @ dt_wo + dt_bo (quad-parallel, weights from smem)
        const int p  = tid >> 2;
        const int l4 = tid & 3;
        float d0 = 0.f, d1 = 0.f, d2 = 0.f;
        const float* row = A + p * AP;
        #pragma unroll 8
        for (int k = l4; k < 128; k += 4) {
            float h = row[k];
            d0 = fmaf(h, W3[k * 3 + 0], d0);
            d1 = fmaf(h, W3[k * 3 + 1], d1);
            d2 = fmaf(h, W3[k * 3 + 2], d2);
        }
        d0 += __shfl_xor_sync(0xffffffffu, d0, 1);
        d0 += __shfl_xor_sync(0xffffffffu, d0, 2);
        d1 += __shfl_xor_sync(0xffffffffu, d1, 1);
        d1 += __shfl_xor_sync(0xffffffffu, d1, 2);
        d2 += __shfl_xor_sync(0xffffffffu, d2, 1);
        d2 += __shfl_xor_sync(0xffffffffu, d2, 2);
        if (l4 == 0) {
            PD[p * 3 + 0] = ray_pts[(size_t)(gbase + p) * 3 + 0] + d0 + W3[384];
            PD[p * 3 + 1] = ray_pts[(size_t)(gbase + p) * 3 + 1] + d1 + W3[385];
            PD[p * 3 + 2] = ray_pts[(size_t)(gbase + p) * 3 + 2] + d2 + W3[386];
        }
    }
    __syncthreads();

    // ---- density -> alpha (tid<64) ; merged 3-scale trilerp ((p,q) threads) --
    if (tid < 64) {
        const int p = tid;
        float t0 = (PD[p * 3 + 0] + 1.f) * 0.5f * 127.f;
        float t1 = (PD[p * 3 + 1] + 1.f) * 0.5f * 127.f;
        float t2 = (PD[p * 3 + 2] + 1.f) * 0.5f * 127.f;
        t0 = fminf(fmaxf(t0, 0.f), 127.f - 1e-4f);
        t1 = fminf(fmaxf(t1, 0.f), 127.f - 1e-4f);
        t2 = fminf(fmaxf(t2, 0.f), 127.f - 1e-4f);
        float f0 = floorf(t0), f1 = floorf(t1), f2 = floorf(t2);
        float dens = tri_gather1(density, GRID_C, (int)f0, (int)f1, (int)f2,
                                 t0 - f0, t1 - f1, t2 - f2);
        float x = dens + ACT_SHIFT_C;
        float sp = (x > 20.f) ? x : log1pf(__expf(x));
        ALP[p] = 1.f - __expf(-sp * 0.5f);
    }
    {
        const int p = tid >> 2, q = tid & 3;
        if (q < 3) {
            float px = PD[p * 3 + 0], py = PD[p * 3 + 1], pz = PD[p * 3 + 2];
            #pragma unroll
            for (int s = 0; s < 3; ++s) {
                const int D = GRID_C >> s;
                const float* gp = (s == 0) ? (const float*)g_feat_t
                                : (s == 1) ? (const float*)g_pool2t
                                           : (const float*)g_pool4t;
                const float dim = (float)(D - 1);
                const float hi = dim - 1e-4f;
                float tx = fminf(fmaxf((px + 1.f) * 0.5f * dim, 0.f), hi);
                float ty = fminf(fmaxf((py + 1.f) * 0.5f * dim, 0.f), hi);
                float tz = fminf(fmaxf((pz + 1.f) * 0.5f * dim, 0.f), hi);
                float flx = floorf(tx), fly = floorf(ty), flz = floorf(tz);
                int ix = (int)flx, iy = (int)fly, iz = (int)flz;
                float fx = tx - flx, fy = ty - fly, fz = tz - flz;
                const size_t sy = (size_t)D * VD_C;
                const size_t sx = (size_t)D * sy;
                const float* b = gp + (size_t)ix * sx + (size_t)iy * sy
                               + (size_t)iz * VD_C + q * 4;
                float4 v000 = __ldg((const float4*)(b));
                float4 v001 = __ldg((const float4*)(b + VD_C));
                float4 v010 = __ldg((const float4*)(b + sy));
                float4 v011 = __ldg((const float4*)(b + sy + VD_C));
                float4 v100 = __ldg((const float4*)(b + sx));
                float4 v101 = __ldg((const float4*)(b + sx + VD_C));
                float4 v110 = __ldg((const float4*)(b + sx + sy));
                float4 v111 = __ldg((const float4*)(b + sx + sy + VD_C));
                float4 c00 = lerp4(v000, v001, fz);
                float4 c01 = lerp4(v010, v011, fz);
                float4 c10 = lerp4(v100, v101, fz);
                float4 c11 = lerp4(v110, v111, fz);
                float4 c0 = lerp4(c00, c01, fy);
                float4 c1 = lerp4(c10, c11, fy);
                float4 r  = lerp4(c0, c1, fx);
                *reinterpret_cast<float4*>(A + p * AP + s * 12 + q * 4) = r;
            }
        }
    }
    __syncthreads();

    if (tid == 0) {  // per-ray exclusive cumprod (overlapped by co-resident block)
        float T = 1.f;
        for (int i = 0; i < PPR_C; ++i) {
            float a = ALP[i];
            WGT[i] = a * T;
            T *= (1.f - a);
        }
        ALAST[0] = T;
    }

    // ---- featurenet input: sin_emb(feat,2)(180) + sin_emb(pts_d,4)(27) ----
    for (int i = tid; i < 64 * 36; i += NTHREADS) {
        int p = i & 63, d = i >> 6;
        float* row = A + p * AP;
        float f = row[d];
        float s1, c1;
        __sincosf(f, &s1, &c1);
        float s2 = 2.f * s1 * c1;
        float c2 = fmaf(-2.f * s1, s1, 1.f);
        row[36 + 2 * d]  = s1;  row[37 + 2 * d]  = s2;
        row[108 + 2 * d] = c1;  row[109 + 2 * d] = c2;
    }
    if (tid < 192) {  // pts_d embedding over 192 threads
        const int p = tid & 63;
        const int d = tid >> 6;
        float* row = A + p * AP;
        float v = PD[p * 3 + d];
        row[180 + d] = v;
        float s, c;
        __sincosf(v, &s, &c);
        row[183 + d * 4] = s;
        row[195 + d * 4] = c;
        #pragma unroll
        for (int k = 1; k < 4; ++k) {
            float s2 = 2.f * s * c;
            float c2 = fmaf(-2.f * s, s, 1.f);
            s = s2; c = c2;
            row[183 + d * 4 + k] = s;
            row[195 + d * 4 + k] = c;
        }
        if (d == 0) row[207] = 0.f;   // guards garbage weight row 207
    }
    __syncthreads();

    // ---- featurenet + folded decoder ----
    mlp_layer<128, 1>(fn_w0, fn_b0, A, AP, 207, 208, Bb, BP, WS,
                      mbF, mbE, phF, phE, gt, tid);
    __syncthreads();
    // dec' = relu(hf @ g_decw + DB0)   (dec_wf folded into dec_w0)
    mlp_layer<64, 1>(g_decw, DB0, Bb, BP, 128, 128, A, AP, WS,
                     mbF, mbE, phF, phE, gt, tid);
    __syncthreads();

    {   // final 64->3 + sigmoid (quad-parallel, weights from smem)
        const int p  = tid >> 2;
        const int l4 = tid & 3;
        float r0 = 0.f, r1 = 0.f, r2 = 0.f;
        const float* row = A + p * AP;
        #pragma unroll 4
        for (int k = l4; k < 64; k += 4) {
            float h = row[k];
            r0 = fmaf(h, W3B[k * 3 + 0], r0);
            r1 = fmaf(h, W3B[k * 3 + 1], r1);
            r2 = fmaf(h, W3B[k * 3 + 2], r2);
        }
        r0 += __shfl_xor_sync(0xffffffffu, r0, 1);
        r0 += __shfl_xor_sync(0xffffffffu, r0, 2);
        r1 += __shfl_xor_sync(0xffffffffu, r1, 1);
        r1 += __shfl_xor_sync(0xffffffffu, r1, 2);
        r2 += __shfl_xor_sync(0xffffffffu, r2, 1);
        r2 += __shfl_xor_sync(0xffffffffu, r2, 2);
        if (l4 == 0) {
            r0 += W3B[192]; r1 += W3B[193]; r2 += W3B[194];
            RGB[p * 3 + 0] = 1.f / (1.f + __expf(-r0));
            RGB[p * 3 + 1] = 1.f / (1.f + __expf(-r1));
            RGB[p * 3 + 2] = 1.f / (1.f + __expf(-r2));
        }
    }
    __syncthreads();

    if (tid < 3) {  // composite with white background
        float s = ALAST[0];
        for (int p = 0; p < PPR_C; ++p) s = fmaf(WGT[p], RGB[p * 3 + tid], s);
        out[(size_t)ray * 3 + tid] = s;
    }
}

// ---------------- launch ----------------
extern "C" void kernel_launch(void* const* d_in, const int* in_sizes, int n_in,
                              void* d_out, int out_size) {
    (void)in_sizes; (void)n_in; (void)out_size;
    const float* ray_pts    = (const float*)d_in[0];
    const float* viewdirs   = (const float*)d_in[1];
    const float* frame_time = (const float*)d_in[2];
    const float* feature    = (const float*)d_in[3];
    const float* density    = (const float*)d_in[4];
    const float* tn_w0 = (const float*)d_in[5];
    const float* tn_b0 = (const float*)d_in[6];
    const float* tn_w1 = (const float*)d_in[7];
    const float* tn_b1 = (const float*)d_in[8];
    const float* dt_w0 = (const float*)d_in[9];
    const float* dt_b0 = (const float*)d_in[10];
    const float* dt_w1 = (const float*)d_in[11];
    const float* dt_b1 = (const float*)d_in[12];
    const float* dt_wo = (const float*)d_in[13];
    const float* dt_bo = (const float*)d_in[14];
    const float* fn_w0 = (const float*)d_in[15];
    const float* fn_b0 = (const float*)d_in[16];
    const float* dec_wf = (const float*)d_in[17];
    const float* dec_bf = (const float*)d_in[18];
    const float* dec_w0 = (const float*)d_in[19];
    const float* dec_b0 = (const float*)d_in[20];
    const float* dec_w1 = (const float*)d_in[21];
    const float* dec_b1 = (const float*)d_in[22];
    float* out = (float*)d_out;

    cudaFuncSetAttribute(voxelmlp_main, cudaFuncAttributeMaxDynamicSharedMemorySize,
                         SMEM_BYTES);

    {
        const int V = GRID_C * GRID_C * GRID_C;
        transpose_feat<<<(V + 255) / 256, 256>>>(feature);
    }
    pool2t_kernel<<<(64 * 64 * 64 + 255) / 256, 256>>>();
    pool4t_kernel<<<(32 * 32 * 32 + 255) / 256, 256>>>();
    timenet_kernel<<<1, 128>>>(frame_time, tn_w0, tn_b0, tn_w1, tn_b1,
                               dt_w0, dt_b0);
    fold_dec<<<129, 64>>>(dec_wf, dec_bf, dec_w0, dec_b0);

    voxelmlp_main<<<N_RAYS_C, NTHREADS, SMEM_BYTES>>>(
        ray_pts, viewdirs, density,
        dt_w0, dt_w1, dt_b1, dt_wo, dt_bo,
        fn_w0, fn_b0, dec_w0, dec_w1, dec_b1,
        out);
}